// round 12
// baseline (speedup 1.0000x reference)
#include <cuda_runtime.h>
#include <math.h>

#define BB 16
#define NPT 4096
#define SS 1024
#define KS 32
#define DF 64
#define C0 67
#define C1 64
#define C2 64
#define C3 128
#define RR 16
#define PP (BB*SS*KS)            // 524288 positions

#define OUT_XYZ_OFF 0
#define OUT_NP_OFF  ((size_t)BB*SS*3)
#define OUT_FPS_OFF ((size_t)BB*SS*3 + (size_t)BB*SS*C3)

// ---------------- scratch (static device arrays; no allocs) ----------------
__device__ int      d_fps[BB*SS];
__device__ int      d_knn[BB*SS*KS];
__device__ float    d_y0[(size_t)C1*PP];        // channel-major [c][pos]
__device__ float    d_y1[(size_t)C2*PP];
__device__ unsigned d_rawmax[(size_t)BB*SS*C3]; // per-(row,ch) max of raw y2, keyed
__device__ float    d_np[(size_t)BB*SS*C3];     // pooled, row-major [r][c]
__device__ double   d_sum[3*128];
__device__ double   d_sq[3*128];
__device__ float    d_mu[3*128];
__device__ float    d_rs[3*128];
__device__ double   d_avgsum[BB*C3];
__device__ unsigned d_maxb[BB*C3];
__device__ float    d_scale[BB*C3];

// packed f32x2 FMA (bit-identical 2x fp32 FMA)
__device__ __forceinline__ unsigned long long ffma2(unsigned long long a,
                                                    unsigned long long b,
                                                    unsigned long long c) {
    unsigned long long d;
    asm("fma.rn.f32x2 %0, %1, %2, %3;" : "=l"(d) : "l"(a), "l"(b), "l"(c));
    return d;
}
__device__ __forceinline__ float2 unpack2(unsigned long long v) {
    float2 r;
    r.x = __uint_as_float((unsigned)v);
    r.y = __uint_as_float((unsigned)(v >> 32));
    return r;
}
__device__ __forceinline__ unsigned long long dup2(float x) {
    unsigned long long r;
    asm("mov.b64 %0, {%1, %1};" : "=l"(r) : "r"(__float_as_uint(x)));
    return r;
}

// order-preserving float<->uint key (all finite floats)
__device__ __forceinline__ unsigned mkey(float f) {
    unsigned b = __float_as_uint(f);
    return (b & 0x80000000u) ? ~b : (b | 0x80000000u);
}
__device__ __forceinline__ float unkey(unsigned k) {
    unsigned b = (k & 0x80000000u) ? (k & 0x7fffffffu) : ~k;
    return __uint_as_float(b);
}

// ---------------- zero accumulators ----------------------------------------
__global__ void kzero() {
    int t = blockIdx.x * blockDim.x + threadIdx.x;
    if (t < 3*128) { d_sum[t] = 0.0; d_sq[t] = 0.0; }
    if (t < BB*C3) { d_avgsum[t] = 0.0; d_maxb[t] = 0u; }
}

// ---------------- K1: farthest point sampling (1 block / batch) ------------
__global__ __launch_bounds__(512) void kfps(const float* __restrict__ xyz, float* __restrict__ out) {
    int b = blockIdx.x;
    extern __shared__ float sh[];
    float* sx = sh;
    float* sy = sh + NPT;
    float* sz = sh + 2*NPT;
    __shared__ unsigned rb[2][16];
    __shared__ int      ri[2][16];

    int t = threadIdx.x;
    int lane = t & 31, wid = t >> 5;
    const float* xb = xyz + (size_t)b * NPT * 3;
    for (int p = t; p < NPT; p += 512) {
        sx[p] = xb[3*p]; sy[p] = xb[3*p+1]; sz[p] = xb[3*p+2];
    }
    __syncthreads();

    float px[8], py[8], pz[8], dist[8];
#pragma unroll
    for (int j = 0; j < 8; j++) {
        int p = j*512 + t;
        px[j] = sx[p]; py[j] = sy[p]; pz[j] = sz[p];
        dist[j] = INFINITY;
    }

    int far = NPT / 2;
    int ph = 0;
    for (int i = 0; i < SS; i++) {
        if (t == 0) {
            d_fps[b*SS + i] = far;
            out[OUT_XYZ_OFF + (size_t)(b*SS + i)*3 + 0] = sx[far];
            out[OUT_XYZ_OFF + (size_t)(b*SS + i)*3 + 1] = sy[far];
            out[OUT_XYZ_OFF + (size_t)(b*SS + i)*3 + 2] = sz[far];
            out[OUT_FPS_OFF + b*SS + i] = (float)far;
        }
        if (i == SS - 1) break;   // last centroid's successor is never used
        float cx = sx[far], cy = sy[far], cz = sz[far];
        float bv = -1.0f; int bi = 0;
#pragma unroll
        for (int j = 0; j < 8; j++) {
            float dx = __fadd_rn(px[j], -cx);
            float dy = __fadd_rn(py[j], -cy);
            float dz = __fadd_rn(pz[j], -cz);
            float d = __fadd_rn(__fadd_rn(__fmul_rn(dx,dx), __fmul_rn(dy,dy)),
                                __fmul_rn(dz,dz));
            float nd = fminf(dist[j], d);
            dist[j] = nd;
            if (nd > bv) { bv = nd; bi = j*512 + t; }  // lowest idx kept on tie
        }
        unsigned db = __float_as_uint(bv);
        unsigned m  = __reduce_max_sync(0xffffffffu, db);
        unsigned ii = (db == m) ? (unsigned)bi : 0xffffffffu;
        unsigned wi = __reduce_min_sync(0xffffffffu, ii);
        if (lane == 0) { rb[ph][wid] = m; ri[ph][wid] = (int)wi; }
        __syncthreads();
        unsigned m2 = (lane < 16) ? rb[ph][lane] : 0u;
        unsigned mm = __reduce_max_sync(0xffffffffu, m2);
        unsigned i2 = (lane < 16 && m2 == mm) ? (unsigned)ri[ph][lane] : 0xffffffffu;
        far = (int)__reduce_min_sync(0xffffffffu, i2);
        ph ^= 1;
    }
}

// ---------------- K2: 32-NN per sampled point (warp per query) -------------
__global__ void kknn(const float* __restrict__ xyz) {
    int warp = (blockIdx.x * blockDim.x + threadIdx.x) >> 5;
    int lane = threadIdx.x & 31;
    if (warp >= BB*SS) return;
    int b = warp / SS;
    int qi = d_fps[warp];
    const float* xb = xyz + (size_t)b * NPT * 3;
    float qx = xb[3*qi], qy = xb[3*qi+1], qz = xb[3*qi+2];
    float ss2 = qx*qx + qy*qy + qz*qz;

    auto distf = [&](int n) {
        float x = xb[3*n], y = xb[3*n+1], z = xb[3*n+2];
        float dot = x*qx + y*qy + z*qz;
        float nn2 = x*x + y*y + z*z;
        return -2.0f*dot + ss2 + nn2;
    };

    float hd = distf(lane);
    int   hi = lane;
    float md; int mi, ml;
    auto worst32 = [&]() {
        unsigned key = __float_as_uint(hd);       // dists >= 0
        unsigned m = __reduce_max_sync(0xffffffffu, key);
        unsigned im = __reduce_max_sync(0xffffffffu,
                          (key == m) ? (unsigned)hi : 0u);
        unsigned lm = __ballot_sync(0xffffffffu,
                          (key == m) && ((unsigned)hi == im));
        md = __uint_as_float(m);
        mi = (int)im;
        ml = 31 - __clz(lm);
    };
    worst32();

    for (int it = 1; it < NPT/32; it++) {
        int n = it*32 + lane;
        float dc = distf(n);
        bool pr = (dc < md) || (dc == md && n < mi);
        unsigned mask = __ballot_sync(0xffffffffu, pr);
        while (mask) {
            int l = __ffs(mask) - 1; mask &= mask - 1;
            float cd = __shfl_sync(0xffffffffu, dc, l);
            int   ci = it*32 + l;
            if (cd < md || (cd == md && ci < mi)) {
                if (lane == ml) { hd = cd; hi = ci; }
                worst32();
            }
        }
    }
    d_knn[warp*KS + lane] = hi;
}

// ---------------- K3: gather + layer0 GEMM + stats -------------------------
// Block: 64 out x 128 pos, 256 thr. Thread: 8 out (4 natural pairs) x 4 pos.
// tx=t&31 (pos quad), ty=t>>5 (8-out group). FFMA2 pairs over OUTPUTS.
__global__ __launch_bounds__(256, 3) void klayer0(const float* __restrict__ xyz,
                        const float* __restrict__ pts,
                        const float* __restrict__ W,
                        const float* __restrict__ bias) {
    extern __shared__ float sm[];
    float*  sH  = sm;                      // [C0][128]
    float*  sWt = sH + C0*128;             // [C0][C1] transposed
    float*  sb  = sWt + C0*C1;             // [C1]
    double* ssum = (double*)(sb + C1);     // [C1]
    double* ssq  = ssum + C1;

    int t = threadIdx.x;
    for (int i = t; i < C0*C1; i += 256) {
        int o = i & (C1-1), k = i >> 6;     // C1 = 64
        sWt[k*C1 + o] = W[o*C0 + k];
    }
    if (t < C1) { sb[t] = bias[t]; ssum[t] = 0.0; ssq[t] = 0.0; }

    int pos0 = blockIdx.x * 128;
    {   // gather: 2 threads per position (half = t&1)
        int p = t >> 1, half = t & 1;
        int pos = pos0 + p;
        int n  = d_knn[pos];
        int b  = pos >> 15;
        const float* pbase = pts + ((size_t)b*NPT + n) * DF;
        if (half == 0) {
            int qi = d_fps[pos >> 5];
            const float* xb = xyz + (size_t)b * NPT * 3;
            sH[0*128 + p] = xb[3*n]   - xb[3*qi];
            sH[1*128 + p] = xb[3*n+1] - xb[3*qi+1];
            sH[2*128 + p] = xb[3*n+2] - xb[3*qi+2];
        }
        const float4* pb = (const float4*)pbase;
#pragma unroll
        for (int c4 = half*8; c4 < half*8 + 8; c4++) {
            float4 v = pb[c4];
            sH[(3+4*c4+0)*128 + p] = v.x;
            sH[(3+4*c4+1)*128 + p] = v.y;
            sH[(3+4*c4+2)*128 + p] = v.z;
            sH[(3+4*c4+3)*128 + p] = v.w;
        }
    }
    __syncthreads();

    int tx = t & 31, ty = t >> 5;
    unsigned long long acc[4][4];
#pragma unroll
    for (int i = 0; i < 4; i++)
#pragma unroll
        for (int j = 0; j < 4; j++) acc[i][j] = 0ull;

    for (int k = 0; k < C0; k++) {
        float4 h = *(const float4*)(sH + k*128 + tx*4);
        unsigned long long hv[4] = {dup2(h.x), dup2(h.y), dup2(h.z), dup2(h.w)};
        const ulonglong2* wp = (const ulonglong2*)(sWt + k*C1 + ty*8);
        ulonglong2 wa = wp[0], wb = wp[1];
        unsigned long long wv[4] = {wa.x, wa.y, wb.x, wb.y};
#pragma unroll
        for (int i = 0; i < 4; i++)
#pragma unroll
            for (int j = 0; j < 4; j++) acc[i][j] = ffma2(wv[i], hv[j], acc[i][j]);
    }

    int lane = t & 31;
#pragma unroll
    for (int i = 0; i < 4; i++) {
        int co0 = ty*8 + 2*i, co1 = co0 + 1;
        float b0 = sb[co0], b1 = sb[co1];
        float2 p0 = unpack2(acc[i][0]), p1 = unpack2(acc[i][1]);
        float2 p2 = unpack2(acc[i][2]), p3 = unpack2(acc[i][3]);
        float4 vA = make_float4(p0.x+b0, p1.x+b0, p2.x+b0, p3.x+b0);
        float4 vB = make_float4(p0.y+b1, p1.y+b1, p2.y+b1, p3.y+b1);
        *(float4*)(d_y0 + (size_t)co0*PP + pos0 + tx*4) = vA;
        *(float4*)(d_y0 + (size_t)co1*PP + pos0 + tx*4) = vB;
        float s1A = vA.x+vA.y+vA.z+vA.w;
        float s2A = vA.x*vA.x+vA.y*vA.y+vA.z*vA.z+vA.w*vA.w;
        float s1B = vB.x+vB.y+vB.z+vB.w;
        float s2B = vB.x*vB.x+vB.y*vB.y+vB.z*vB.z+vB.w*vB.w;
#pragma unroll
        for (int off = 16; off; off >>= 1) {
            s1A += __shfl_xor_sync(0xffffffffu, s1A, off);
            s2A += __shfl_xor_sync(0xffffffffu, s2A, off);
            s1B += __shfl_xor_sync(0xffffffffu, s1B, off);
            s2B += __shfl_xor_sync(0xffffffffu, s2B, off);
        }
        if (lane == 0) {
            atomicAdd(&ssum[co0], (double)s1A); atomicAdd(&ssq[co0], (double)s2A);
            atomicAdd(&ssum[co1], (double)s1B); atomicAdd(&ssq[co1], (double)s2B);
        }
    }
    __syncthreads();
    if (t < C1) { atomicAdd(&d_sum[t], ssum[t]); atomicAdd(&d_sq[t], ssq[t]); }
}

// ---------------- finalize BN stats ----------------------------------------
__global__ void kstats(int L, int C) {
    int c = threadIdx.x;
    if (c < C) {
        double cnt = (double)PP;
        double mu  = d_sum[L*128 + c] / cnt;
        double var = d_sq[L*128 + c] / cnt - mu*mu;
        d_mu[L*128 + c] = (float)mu;
        d_rs[L*128 + c] = (float)(1.0 / sqrt(var + 1e-5));
    }
}

// ---------------- K5: layer1 GEMM (64->64), bn0+relu on load ---------------
// Block: 64 out x 128 pos, same tiling as klayer0.
__global__ __launch_bounds__(256, 3) void kmid64(const float* __restrict__ W,
                       const float* __restrict__ bias,
                       const float* __restrict__ gam,
                       const float* __restrict__ bet) {
    extern __shared__ float sm[];
    float*  sH  = sm;                      // [64][128]
    float*  sWt = sH + 64*128;             // [64][64]
    float*  smu = sWt + 64*64;
    float*  srs = smu + 64;
    float*  sga = srs + 64;
    float*  sbe = sga + 64;
    float*  sb  = sbe + 64;
    double* ssum = (double*)(sb + 64);
    double* ssq  = ssum + 64;

    int t = threadIdx.x;
    for (int i = t; i < 64*64; i += 256) {
        int o = i & 63, k = i >> 6;
        sWt[k*64 + o] = W[o*64 + k];
    }
    if (t < 64) {
        smu[t] = d_mu[t]; srs[t] = d_rs[t];
        sga[t] = gam[t];  sbe[t] = bet[t];
        sb[t] = bias[t]; ssum[t] = 0.0; ssq[t] = 0.0;
    }
    __syncthreads();

    int pos0 = blockIdx.x * 128;
    for (int i = t; i < 64*32; i += 256) {        // 64 ch x 32 float4
        int c = i >> 5, p4 = i & 31;
        float4 v = *(const float4*)(d_y0 + (size_t)c*PP + pos0 + p4*4);
        float mu = smu[c], rs = srs[c], ga = sga[c], be = sbe[c];
        float a0 = ga*(v.x-mu); a0 *= rs; a0 += be; a0 = fmaxf(a0, 0.f);
        float a1 = ga*(v.y-mu); a1 *= rs; a1 += be; a1 = fmaxf(a1, 0.f);
        float a2 = ga*(v.z-mu); a2 *= rs; a2 += be; a2 = fmaxf(a2, 0.f);
        float a3 = ga*(v.w-mu); a3 *= rs; a3 += be; a3 = fmaxf(a3, 0.f);
        *(float4*)(sH + c*128 + p4*4) = make_float4(a0,a1,a2,a3);
    }
    __syncthreads();

    int tx = t & 31, ty = t >> 5;
    unsigned long long acc[4][4];
#pragma unroll
    for (int i = 0; i < 4; i++)
#pragma unroll
        for (int j = 0; j < 4; j++) acc[i][j] = 0ull;

    for (int k = 0; k < 64; k++) {
        float4 h = *(const float4*)(sH + k*128 + tx*4);
        unsigned long long hv[4] = {dup2(h.x), dup2(h.y), dup2(h.z), dup2(h.w)};
        const ulonglong2* wp = (const ulonglong2*)(sWt + k*64 + ty*8);
        ulonglong2 wa = wp[0], wb = wp[1];
        unsigned long long wv[4] = {wa.x, wa.y, wb.x, wb.y};
#pragma unroll
        for (int i = 0; i < 4; i++)
#pragma unroll
            for (int j = 0; j < 4; j++) acc[i][j] = ffma2(wv[i], hv[j], acc[i][j]);
    }

    int lane = t & 31;
#pragma unroll
    for (int i = 0; i < 4; i++) {
        int co0 = ty*8 + 2*i, co1 = co0 + 1;
        float b0 = sb[co0], b1 = sb[co1];
        float2 p0 = unpack2(acc[i][0]), p1 = unpack2(acc[i][1]);
        float2 p2 = unpack2(acc[i][2]), p3 = unpack2(acc[i][3]);
        float4 vA = make_float4(p0.x+b0, p1.x+b0, p2.x+b0, p3.x+b0);
        float4 vB = make_float4(p0.y+b1, p1.y+b1, p2.y+b1, p3.y+b1);
        *(float4*)(d_y1 + (size_t)co0*PP + pos0 + tx*4) = vA;
        *(float4*)(d_y1 + (size_t)co1*PP + pos0 + tx*4) = vB;
        float s1A = vA.x+vA.y+vA.z+vA.w;
        float s2A = vA.x*vA.x+vA.y*vA.y+vA.z*vA.z+vA.w*vA.w;
        float s1B = vB.x+vB.y+vB.z+vB.w;
        float s2B = vB.x*vB.x+vB.y*vB.y+vB.z*vB.z+vB.w*vB.w;
#pragma unroll
        for (int off = 16; off; off >>= 1) {
            s1A += __shfl_xor_sync(0xffffffffu, s1A, off);
            s2A += __shfl_xor_sync(0xffffffffu, s2A, off);
            s1B += __shfl_xor_sync(0xffffffffu, s1B, off);
            s2B += __shfl_xor_sync(0xffffffffu, s2B, off);
        }
        if (lane == 0) {
            atomicAdd(&ssum[co0], (double)s1A); atomicAdd(&ssq[co0], (double)s2A);
            atomicAdd(&ssum[co1], (double)s1B); atomicAdd(&ssq[co1], (double)s2B);
        }
    }
    __syncthreads();
    if (t < 64) { atomicAdd(&d_sum[128 + t], ssum[t]); atomicAdd(&d_sq[128 + t], ssq[t]); }
}

// ---------------- K7: layer2 GEMM (64->128) + stats + raw max-pool ---------
// Block: 128 out x 64 pos (2 rows). tx=t&15 (pos quad), ty=t>>4 (8-out group).
__global__ __launch_bounds__(256, 3) void klast(const float* __restrict__ W,
                      const float* __restrict__ bias,
                      const float* __restrict__ gam,
                      const float* __restrict__ bet) {
    extern __shared__ float sm[];
    float*    sH   = sm;                     // [64][64]
    float*    sWt  = sH + 64*64;             // [64][128]
    float*    smu  = sWt + 64*128;
    float*    srs  = smu + 64;
    float*    sga  = srs + 64;
    float*    sbe  = sga + 64;
    float*    sb   = sbe + 64;               // [128]
    unsigned* smax = (unsigned*)(sb + 128);  // [2][128]
    double*   ssum = (double*)(smax + 2*128);
    double*   ssq  = ssum + 128;

    int t = threadIdx.x;
    for (int i = t; i < 64*128; i += 256) {
        int o = i & 127, k = i >> 7;
        sWt[k*128 + o] = W[o*64 + k];
    }
    if (t < 64) {
        smu[t] = d_mu[128 + t]; srs[t] = d_rs[128 + t];
        sga[t] = gam[t];        sbe[t] = bet[t];
    }
    if (t < 128) { sb[t] = bias[t]; ssum[t] = 0.0; ssq[t] = 0.0; }
    if (t < 256) { if (t < 2*128) smax[t] = 0u; }
    __syncthreads();

    int pos0 = blockIdx.x * 64;
    for (int i = t; i < 64*16; i += 256) {         // 64 ch x 16 float4
        int c = i >> 4, p4 = i & 15;
        float4 v = *(const float4*)(d_y1 + (size_t)c*PP + pos0 + p4*4);
        float mu = smu[c], rs = srs[c], ga = sga[c], be = sbe[c];
        float a0 = ga*(v.x-mu); a0 *= rs; a0 += be; a0 = fmaxf(a0, 0.f);
        float a1 = ga*(v.y-mu); a1 *= rs; a1 += be; a1 = fmaxf(a1, 0.f);
        float a2 = ga*(v.z-mu); a2 *= rs; a2 += be; a2 = fmaxf(a2, 0.f);
        float a3 = ga*(v.w-mu); a3 *= rs; a3 += be; a3 = fmaxf(a3, 0.f);
        *(float4*)(sH + c*64 + p4*4) = make_float4(a0,a1,a2,a3);
    }
    __syncthreads();

    int tx = t & 15, ty = t >> 4;
    unsigned long long acc[4][4];
#pragma unroll
    for (int i = 0; i < 4; i++)
#pragma unroll
        for (int j = 0; j < 4; j++) acc[i][j] = 0ull;

    for (int k = 0; k < 64; k++) {
        float4 h = *(const float4*)(sH + k*64 + tx*4);
        unsigned long long hv[4] = {dup2(h.x), dup2(h.y), dup2(h.z), dup2(h.w)};
        const ulonglong2* wp = (const ulonglong2*)(sWt + k*128 + ty*8);
        ulonglong2 wa = wp[0], wb = wp[1];
        unsigned long long wv[4] = {wa.x, wa.y, wb.x, wb.y};
#pragma unroll
        for (int i = 0; i < 4; i++)
#pragma unroll
            for (int j = 0; j < 4; j++) acc[i][j] = ffma2(wv[i], hv[j], acc[i][j]);
    }

#pragma unroll
    for (int i = 0; i < 4; i++) {
        int co0 = ty*8 + 2*i, co1 = co0 + 1;
        float b0 = sb[co0], b1 = sb[co1];
        float2 p0 = unpack2(acc[i][0]), p1 = unpack2(acc[i][1]);
        float2 p2 = unpack2(acc[i][2]), p3 = unpack2(acc[i][3]);
        float a0 = p0.x+b0, a1 = p1.x+b0, a2 = p2.x+b0, a3 = p3.x+b0;
        float c0 = p0.y+b1, c1 = p1.y+b1, c2 = p2.y+b1, c3 = p3.y+b1;
        float lA = fmaxf(fmaxf(a0,a1), fmaxf(a2,a3));
        float lB = fmaxf(fmaxf(c0,c1), fmaxf(c2,c3));
        float s1A = a0+a1+a2+a3, s2A = a0*a0+a1*a1+a2*a2+a3*a3;
        float s1B = c0+c1+c2+c3, s2B = c0*c0+c1*c1+c2*c2+c3*c3;
        // stats: reduce over the 16-lane tx group (xor 8..1 stays in-group)
#pragma unroll
        for (int off = 8; off; off >>= 1) {
            s1A += __shfl_xor_sync(0xffffffffu, s1A, off);
            s2A += __shfl_xor_sync(0xffffffffu, s2A, off);
            s1B += __shfl_xor_sync(0xffffffffu, s1B, off);
            s2B += __shfl_xor_sync(0xffffffffu, s2B, off);
        }
        if (tx == 0) {
            atomicAdd(&ssum[co0], (double)s1A); atomicAdd(&ssq[co0], (double)s2A);
            atomicAdd(&ssum[co1], (double)s1B); atomicAdd(&ssq[co1], (double)s2B);
        }
        // positions tx*4..tx*4+3 lie within the 32-pos window tx>>3 (0 or 1)
        atomicMax(&smax[(tx >> 3)*128 + co0], mkey(lA));
        atomicMax(&smax[(tx >> 3)*128 + co1], mkey(lB));
    }
    __syncthreads();
    if (t < 2*128) {
        int r = (pos0 >> 5) + (t >> 7);
        d_rawmax[(size_t)r*C3 + (t & 127)] = smax[t];
    }
    if (t < 128) { atomicAdd(&d_sum[256 + t], ssum[t]); atomicAdd(&d_sq[256 + t], ssq[t]); }
}

// ---------------- K9: decode raw max, bn2+relu, attention partials ---------
__global__ void kpool(const float* __restrict__ gam, const float* __restrict__ bet) {
    int t = threadIdx.x;
    int c = t & 127, half = t >> 7;
    int blk = blockIdx.x;                  // 256 blocks, 16 per batch
    int b = blk >> 4;
    int r0 = blk * 64 + half * 32;
    float mu = d_mu[256 + c], rs = d_rs[256 + c];
    float ga = gam[c], be = bet[c];
    float sum = 0.0f, mx = 0.0f;
    for (int rr = 0; rr < 32; rr++) {
        int r = r0 + rr;
        float f = unkey(d_rawmax[(size_t)r*C3 + c]);
        float v = ga*(f - mu); v *= rs; v += be; v = fmaxf(v, 0.0f);
        d_np[(size_t)r*C3 + c] = v;
        sum += v; mx = fmaxf(mx, v);
    }
    __shared__ float ssm[256], smm[256];
    ssm[t] = sum; smm[t] = mx;
    __syncthreads();
    if (t < 128) {
        sum = ssm[t] + ssm[t + 128];
        mx = fmaxf(smm[t], smm[t + 128]);
        atomicAdd(&d_avgsum[b*C3 + c], (double)sum);
        atomicMax(&d_maxb[b*C3 + c], __float_as_uint(mx)); // v >= 0
    }
}

// ---------------- K10: channel attention (1 block / batch) -----------------
__global__ void katt(const float* __restrict__ aW1, const float* __restrict__ aW2) {
    int b = blockIdx.x;
    int t = threadIdx.x; // 128
    __shared__ float sav[C3], smx[C3], sha[RR], shm[RR];
    sav[t] = (float)(d_avgsum[b*C3 + t] / (double)SS);
    smx[t] = __uint_as_float(d_maxb[b*C3 + t]);
    __syncthreads();
    if (t < RR) {
        float a = 0.0f, m = 0.0f;
        for (int c = 0; c < C3; c++) {
            a = fmaf(aW1[t*C3 + c], sav[c], a);
            m = fmaf(aW1[t*C3 + c], smx[c], m);
        }
        sha[t] = fmaxf(a, 0.0f);
        shm[t] = fmaxf(m, 0.0f);
    }
    __syncthreads();
    float s1 = 0.0f, s2 = 0.0f;
#pragma unroll
    for (int r = 0; r < RR; r++) {
        s1 = fmaf(aW2[t*RR + r], sha[r], s1);
        s2 = fmaf(aW2[t*RR + r], shm[r], s2);
    }
    float x = s1 + s2;
    d_scale[b*C3 + t] = 1.0f / (1.0f + expf(-x));
}

// ---------------- K11: scale + write new_points ----------------------------
__global__ void kout(float* __restrict__ out) {
    size_t i = (size_t)blockIdx.x * 256 + threadIdx.x;
    if (i < (size_t)BB*SS*C3) {
        int c = (int)(i % C3);
        int r = (int)(i / C3);
        int b = r / SS;
        out[OUT_NP_OFF + i] = d_np[i] * d_scale[b*C3 + c];
    }
}

// ---------------------------------------------------------------------------
extern "C" void kernel_launch(void* const* d_in, const int* in_sizes, int n_in,
                              void* d_out, int out_size) {
    const float* xyz  = (const float*)d_in[0];
    const float* pts  = (const float*)d_in[1];
    const float* W0   = (const float*)d_in[2];
    const float* b0   = (const float*)d_in[3];
    const float* g0   = (const float*)d_in[4];
    const float* be0  = (const float*)d_in[5];
    const float* W1   = (const float*)d_in[6];
    const float* b1   = (const float*)d_in[7];
    const float* g1   = (const float*)d_in[8];
    const float* be1  = (const float*)d_in[9];
    const float* W2   = (const float*)d_in[10];
    const float* b2   = (const float*)d_in[11];
    const float* g2   = (const float*)d_in[12];
    const float* be2  = (const float*)d_in[13];
    const float* aW1  = (const float*)d_in[14];
    const float* aW2  = (const float*)d_in[15];
    float* out = (float*)d_out;

    const int SM_FPS  = 3*NPT*4;                                  // 49152
    const int SM_L0   = C0*128*4 + C0*C1*4 + C1*4 + C1*16;        // 52736
    const int SM_L1   = 64*128*4 + 64*64*4 + 5*64*4 + 64*16;      // 51456
    const int SM_L2   = 64*64*4 + 64*128*4 + 4*64*4 + 128*4 + 2*128*4 + 128*16; // 53760

    cudaFuncSetAttribute(kfps,    cudaFuncAttributeMaxDynamicSharedMemorySize, SM_FPS);
    cudaFuncSetAttribute(klayer0, cudaFuncAttributeMaxDynamicSharedMemorySize, SM_L0);
    cudaFuncSetAttribute(kmid64,  cudaFuncAttributeMaxDynamicSharedMemorySize, SM_L1);
    cudaFuncSetAttribute(klast,   cudaFuncAttributeMaxDynamicSharedMemorySize, SM_L2);

    kzero<<<8, 256>>>();
    kfps<<<BB, 512, SM_FPS>>>(xyz, out);
    kknn<<<(BB*SS*32)/256, 256>>>(xyz);
    klayer0<<<PP/128, 256, SM_L0>>>(xyz, pts, W0, b0);
    kstats<<<1, 128>>>(0, C1);
    kmid64<<<PP/128, 256, SM_L1>>>(W1, b1, g0, be0);
    kstats<<<1, 128>>>(1, C2);
    klast<<<PP/64, 256, SM_L2>>>(W2, b2, g1, be1);
    kstats<<<1, 128>>>(2, C3);
    kpool<<<256, 256>>>(g2, be2);
    katt<<<BB, 128>>>(aW1, aW2);
    kout<<<(BB*SS*C3 + 255)/256, 256>>>(out);
}

// round 13
// speedup vs baseline: 1.2084x; 1.2084x over previous
#include <cuda_runtime.h>
#include <math.h>

#define BB 16
#define NPT 4096
#define SS 1024
#define KS 32
#define DF 64
#define C0 67
#define C1 64
#define C2 64
#define C3 128
#define RR 16
#define PP (BB*SS*KS)            // 524288 positions

#define OUT_XYZ_OFF 0
#define OUT_NP_OFF  ((size_t)BB*SS*3)
#define OUT_FPS_OFF ((size_t)BB*SS*3 + (size_t)BB*SS*C3)

// ---------------- scratch (static device arrays; no allocs) ----------------
__device__ int      d_fps[BB*SS];
__device__ int      d_knn[BB*SS*KS];
__device__ float    d_y0[(size_t)C1*PP];        // channel-major [c][pos]
__device__ float    d_y1[(size_t)C2*PP];
__device__ unsigned d_rawmax[(size_t)BB*SS*C3]; // per-(row,ch) max of raw y2, keyed
__device__ float    d_np[(size_t)BB*SS*C3];     // pooled, row-major [r][c]
__device__ double   d_sum[3*128];
__device__ double   d_sq[3*128];
__device__ float    d_mu[3*128];
__device__ float    d_rs[3*128];
__device__ double   d_avgsum[BB*C3];
__device__ unsigned d_maxb[BB*C3];
__device__ float    d_scale[BB*C3];

// ---------------- tf32 helpers ---------------------------------------------
__device__ __forceinline__ unsigned tf32(float x) {
    unsigned r;
    asm("cvt.rna.tf32.f32 %0, %1;" : "=r"(r) : "f"(x));
    return r;
}
__device__ __forceinline__ void mma1688(float& c0, float& c1, float& c2, float& c3,
                                        unsigned a0, unsigned a1, unsigned a2, unsigned a3,
                                        unsigned b0, unsigned b1) {
    asm("mma.sync.aligned.m16n8k8.row.col.f32.tf32.tf32.f32 "
        "{%0,%1,%2,%3}, {%4,%5,%6,%7}, {%8,%9}, {%0,%1,%2,%3};"
        : "+f"(c0), "+f"(c1), "+f"(c2), "+f"(c3)
        : "r"(a0), "r"(a1), "r"(a2), "r"(a3), "r"(b0), "r"(b1));
}

// order-preserving float<->uint key (all finite floats)
__device__ __forceinline__ unsigned mkey(float f) {
    unsigned b = __float_as_uint(f);
    return (b & 0x80000000u) ? ~b : (b | 0x80000000u);
}
__device__ __forceinline__ float unkey(unsigned k) {
    unsigned b = (k & 0x80000000u) ? (k & 0x7fffffffu) : ~k;
    return __uint_as_float(b);
}

// ---------------- zero accumulators ----------------------------------------
__global__ void kzero() {
    int t = blockIdx.x * blockDim.x + threadIdx.x;
    if (t < 3*128) { d_sum[t] = 0.0; d_sq[t] = 0.0; }
    if (t < BB*C3) { d_avgsum[t] = 0.0; d_maxb[t] = 0u; }
}

// ---------------- K1: farthest point sampling (1 block / batch) ------------
__global__ __launch_bounds__(512) void kfps(const float* __restrict__ xyz, float* __restrict__ out) {
    int b = blockIdx.x;
    extern __shared__ float sh[];
    float* sx = sh;
    float* sy = sh + NPT;
    float* sz = sh + 2*NPT;
    __shared__ unsigned rb[2][16];
    __shared__ int      ri[2][16];

    int t = threadIdx.x;
    int lane = t & 31, wid = t >> 5;
    const float* xb = xyz + (size_t)b * NPT * 3;
    for (int p = t; p < NPT; p += 512) {
        sx[p] = xb[3*p]; sy[p] = xb[3*p+1]; sz[p] = xb[3*p+2];
    }
    __syncthreads();

    float px[8], py[8], pz[8], dist[8];
#pragma unroll
    for (int j = 0; j < 8; j++) {
        int p = j*512 + t;
        px[j] = sx[p]; py[j] = sy[p]; pz[j] = sz[p];
        dist[j] = INFINITY;
    }

    int far = NPT / 2;
    int ph = 0;
    for (int i = 0; i < SS; i++) {
        if (t == 0) {
            d_fps[b*SS + i] = far;
            out[OUT_XYZ_OFF + (size_t)(b*SS + i)*3 + 0] = sx[far];
            out[OUT_XYZ_OFF + (size_t)(b*SS + i)*3 + 1] = sy[far];
            out[OUT_XYZ_OFF + (size_t)(b*SS + i)*3 + 2] = sz[far];
            out[OUT_FPS_OFF + b*SS + i] = (float)far;
        }
        if (i == SS - 1) break;   // last centroid's successor is never used
        float cx = sx[far], cy = sy[far], cz = sz[far];
        float bv = -1.0f; int bi = 0;
#pragma unroll
        for (int j = 0; j < 8; j++) {
            float dx = __fadd_rn(px[j], -cx);
            float dy = __fadd_rn(py[j], -cy);
            float dz = __fadd_rn(pz[j], -cz);
            float d = __fadd_rn(__fadd_rn(__fmul_rn(dx,dx), __fmul_rn(dy,dy)),
                                __fmul_rn(dz,dz));
            float nd = fminf(dist[j], d);
            dist[j] = nd;
            if (nd > bv) { bv = nd; bi = j*512 + t; }  // lowest idx kept on tie
        }
        unsigned db = __float_as_uint(bv);
        unsigned m  = __reduce_max_sync(0xffffffffu, db);
        unsigned ii = (db == m) ? (unsigned)bi : 0xffffffffu;
        unsigned wi = __reduce_min_sync(0xffffffffu, ii);
        if (lane == 0) { rb[ph][wid] = m; ri[ph][wid] = (int)wi; }
        __syncthreads();
        unsigned m2 = (lane < 16) ? rb[ph][lane] : 0u;
        unsigned mm = __reduce_max_sync(0xffffffffu, m2);
        unsigned i2 = (lane < 16 && m2 == mm) ? (unsigned)ri[ph][lane] : 0xffffffffu;
        far = (int)__reduce_min_sync(0xffffffffu, i2);
        ph ^= 1;
    }
}

// ---------------- K2: 32-NN per sampled point (warp per query) -------------
__global__ void kknn(const float* __restrict__ xyz) {
    int warp = (blockIdx.x * blockDim.x + threadIdx.x) >> 5;
    int lane = threadIdx.x & 31;
    if (warp >= BB*SS) return;
    int b = warp / SS;
    int qi = d_fps[warp];
    const float* xb = xyz + (size_t)b * NPT * 3;
    float qx = xb[3*qi], qy = xb[3*qi+1], qz = xb[3*qi+2];
    float ss2 = qx*qx + qy*qy + qz*qz;

    auto distf = [&](int n) {
        float x = xb[3*n], y = xb[3*n+1], z = xb[3*n+2];
        float dot = x*qx + y*qy + z*qz;
        float nn2 = x*x + y*y + z*z;
        return -2.0f*dot + ss2 + nn2;
    };

    float hd = distf(lane);
    int   hi = lane;
    float md; int mi, ml;
    auto worst32 = [&]() {
        unsigned key = __float_as_uint(hd);       // dists >= 0
        unsigned m = __reduce_max_sync(0xffffffffu, key);
        unsigned im = __reduce_max_sync(0xffffffffu,
                          (key == m) ? (unsigned)hi : 0u);
        unsigned lm = __ballot_sync(0xffffffffu,
                          (key == m) && ((unsigned)hi == im));
        md = __uint_as_float(m);
        mi = (int)im;
        ml = 31 - __clz(lm);
    };
    worst32();

    for (int it = 1; it < NPT/32; it++) {
        int n = it*32 + lane;
        float dc = distf(n);
        bool pr = (dc < md) || (dc == md && n < mi);
        unsigned mask = __ballot_sync(0xffffffffu, pr);
        while (mask) {
            int l = __ffs(mask) - 1; mask &= mask - 1;
            float cd = __shfl_sync(0xffffffffu, dc, l);
            int   ci = it*32 + l;
            if (cd < md || (cd == md && ci < mi)) {
                if (lane == ml) { hd = cd; hi = ci; }
                worst32();
            }
        }
    }
    d_knn[warp*KS + lane] = hi;
}

// ---------------- K3: gather + layer0 tf32-MMA GEMM + stats ----------------
// Block: 64 out x 128 pos, 256 thr = 8 warps. Warp: 16-out stripe x 64 pos.
// W smem [64][76] (stride 76: A-frag banks 12g+t, conflict-free).
// H smem [72][132] (stride 132: B-frag banks 4t+g, conflict-free); k 67..71 zero.
__global__ __launch_bounds__(256, 3) void klayer0(const float* __restrict__ xyz,
                        const float* __restrict__ pts,
                        const float* __restrict__ W,
                        const float* __restrict__ bias) {
    extern __shared__ unsigned smu_[];
    unsigned* sH = smu_;                 // [72][132]
    unsigned* sW = sH + 72*132;          // [64][76]
    float*    sb = (float*)(sW + 64*76); // [64]
    double*   ssum = (double*)(sb + 64);
    double*   ssq  = ssum + 64;

    int t = threadIdx.x;
    for (int i = t; i < 64*72; i += 256) {
        int o = i / 72, k = i - o*72;
        sW[o*76 + k] = (k < C0) ? tf32(W[o*C0 + k]) : 0u;
    }
    if (t < 64) { sb[t] = bias[t]; ssum[t] = 0.0; ssq[t] = 0.0; }
    for (int i = t; i < 5*132; i += 256)
        sH[(67 + i/132)*132 + (i % 132)] = 0u;

    int pos0 = blockIdx.x * 128;
    {   // gather: 2 threads per position
        int p = t >> 1, half = t & 1;
        int pos = pos0 + p;
        int n  = d_knn[pos];
        int b  = pos >> 15;
        const float* pbase = pts + ((size_t)b*NPT + n) * DF;
        if (half == 0) {
            int qi = d_fps[pos >> 5];
            const float* xb = xyz + (size_t)b * NPT * 3;
            sH[0*132 + p] = tf32(xb[3*n]   - xb[3*qi]);
            sH[1*132 + p] = tf32(xb[3*n+1] - xb[3*qi+1]);
            sH[2*132 + p] = tf32(xb[3*n+2] - xb[3*qi+2]);
        }
        const float4* pb = (const float4*)pbase;
#pragma unroll
        for (int c4 = half*8; c4 < half*8 + 8; c4++) {
            float4 v = pb[c4];
            sH[(3+4*c4+0)*132 + p] = tf32(v.x);
            sH[(3+4*c4+1)*132 + p] = tf32(v.y);
            sH[(3+4*c4+2)*132 + p] = tf32(v.z);
            sH[(3+4*c4+3)*132 + p] = tf32(v.w);
        }
    }
    __syncthreads();

    int lane = t & 31, w = t >> 5;
    int g = lane >> 2, tg = lane & 3;
    int out0 = (w >> 1) * 16;
    int pw   = (w & 1) * 64;

    float acc[8][4];
#pragma unroll
    for (int n = 0; n < 8; n++)
#pragma unroll
        for (int j = 0; j < 4; j++) acc[n][j] = 0.0f;

#pragma unroll
    for (int ks = 0; ks < 9; ks++) {
        int k0 = ks * 8;
        unsigned a0 = sW[(out0+g)*76   + k0 + tg];
        unsigned a1 = sW[(out0+g+8)*76 + k0 + tg];
        unsigned a2 = sW[(out0+g)*76   + k0 + tg + 4];
        unsigned a3 = sW[(out0+g+8)*76 + k0 + tg + 4];
#pragma unroll
        for (int n = 0; n < 8; n++) {
            unsigned b0 = sH[(k0+tg)*132   + pw + n*8 + g];
            unsigned b1 = sH[(k0+tg+4)*132 + pw + n*8 + g];
            mma1688(acc[n][0], acc[n][1], acc[n][2], acc[n][3], a0, a1, a2, a3, b0, b1);
        }
    }

    int r0 = out0 + g, r1 = r0 + 8;
    float bf0 = sb[r0], bf1 = sb[r1];
    float s10 = 0.f, s20 = 0.f, s11 = 0.f, s21 = 0.f;
#pragma unroll
    for (int n = 0; n < 8; n++) {
        float c0 = acc[n][0] + bf0, c1 = acc[n][1] + bf0;
        float c2 = acc[n][2] + bf1, c3 = acc[n][3] + bf1;
        int gp = pos0 + pw + n*8 + 2*tg;
        *(float2*)(d_y0 + (size_t)r0*PP + gp) = make_float2(c0, c1);
        *(float2*)(d_y0 + (size_t)r1*PP + gp) = make_float2(c2, c3);
        s10 += c0 + c1; s20 += c0*c0 + c1*c1;
        s11 += c2 + c3; s21 += c2*c2 + c3*c3;
    }
#pragma unroll
    for (int off = 1; off <= 2; off <<= 1) {
        s10 += __shfl_xor_sync(0xffffffffu, s10, off);
        s20 += __shfl_xor_sync(0xffffffffu, s20, off);
        s11 += __shfl_xor_sync(0xffffffffu, s11, off);
        s21 += __shfl_xor_sync(0xffffffffu, s21, off);
    }
    if (tg == 0) {
        atomicAdd(&ssum[r0], (double)s10); atomicAdd(&ssq[r0], (double)s20);
        atomicAdd(&ssum[r1], (double)s11); atomicAdd(&ssq[r1], (double)s21);
    }
    __syncthreads();
    if (t < 64) { atomicAdd(&d_sum[t], ssum[t]); atomicAdd(&d_sq[t], ssq[t]); }
}

// ---------------- finalize BN stats ----------------------------------------
__global__ void kstats(int L, int C) {
    int c = threadIdx.x;
    if (c < C) {
        double cnt = (double)PP;
        double mu  = d_sum[L*128 + c] / cnt;
        double var = d_sq[L*128 + c] / cnt - mu*mu;
        d_mu[L*128 + c] = (float)mu;
        d_rs[L*128 + c] = (float)(1.0 / sqrt(var + 1e-5));
    }
}

// ---------------- K5: layer1 tf32-MMA GEMM (64->64), bn0+relu on load ------
// Block 64 out x 128 pos. W smem [64][68], H smem [64][132].
__global__ __launch_bounds__(256, 3) void kmid64(const float* __restrict__ W,
                       const float* __restrict__ bias,
                       const float* __restrict__ gam,
                       const float* __restrict__ bet) {
    extern __shared__ unsigned smu_[];
    unsigned* sH = smu_;                  // [64][132]
    unsigned* sW = sH + 64*132;           // [64][68]
    float*    smu = (float*)(sW + 64*68); // [64] x4
    float*    srs = smu + 64;
    float*    sga = srs + 64;
    float*    sbe = sga + 64;
    float*    sb  = sbe + 64;
    double*   ssum = (double*)(sb + 64);
    double*   ssq  = ssum + 64;

    int t = threadIdx.x;
    for (int i = t; i < 64*68; i += 256) {
        int o = i / 68, k = i - o*68;
        sW[o*68 + k] = (k < 64) ? tf32(W[o*64 + k]) : 0u;
    }
    if (t < 64) {
        smu[t] = d_mu[t]; srs[t] = d_rs[t];
        sga[t] = gam[t];  sbe[t] = bet[t];
        sb[t] = bias[t]; ssum[t] = 0.0; ssq[t] = 0.0;
    }
    __syncthreads();

    int pos0 = blockIdx.x * 128;
    for (int i = t; i < 64*32; i += 256) {        // 64 ch x 32 float4
        int c = i >> 5, p4 = i & 31;
        float4 v = *(const float4*)(d_y0 + (size_t)c*PP + pos0 + p4*4);
        float mu = smu[c], rs = srs[c], ga = sga[c], be = sbe[c];
        float a0 = ga*(v.x-mu); a0 *= rs; a0 += be; a0 = fmaxf(a0, 0.f);
        float a1 = ga*(v.y-mu); a1 *= rs; a1 += be; a1 = fmaxf(a1, 0.f);
        float a2 = ga*(v.z-mu); a2 *= rs; a2 += be; a2 = fmaxf(a2, 0.f);
        float a3 = ga*(v.w-mu); a3 *= rs; a3 += be; a3 = fmaxf(a3, 0.f);
        uint4 u; u.x = tf32(a0); u.y = tf32(a1); u.z = tf32(a2); u.w = tf32(a3);
        *(uint4*)(sH + c*132 + p4*4) = u;
    }
    __syncthreads();

    int lane = t & 31, w = t >> 5;
    int g = lane >> 2, tg = lane & 3;
    int out0 = (w >> 1) * 16;
    int pw   = (w & 1) * 64;

    float acc[8][4];
#pragma unroll
    for (int n = 0; n < 8; n++)
#pragma unroll
        for (int j = 0; j < 4; j++) acc[n][j] = 0.0f;

#pragma unroll
    for (int ks = 0; ks < 8; ks++) {
        int k0 = ks * 8;
        unsigned a0 = sW[(out0+g)*68   + k0 + tg];
        unsigned a1 = sW[(out0+g+8)*68 + k0 + tg];
        unsigned a2 = sW[(out0+g)*68   + k0 + tg + 4];
        unsigned a3 = sW[(out0+g+8)*68 + k0 + tg + 4];
#pragma unroll
        for (int n = 0; n < 8; n++) {
            unsigned b0 = sH[(k0+tg)*132   + pw + n*8 + g];
            unsigned b1 = sH[(k0+tg+4)*132 + pw + n*8 + g];
            mma1688(acc[n][0], acc[n][1], acc[n][2], acc[n][3], a0, a1, a2, a3, b0, b1);
        }
    }

    int r0 = out0 + g, r1 = r0 + 8;
    float bf0 = sb[r0], bf1 = sb[r1];
    float s10 = 0.f, s20 = 0.f, s11 = 0.f, s21 = 0.f;
#pragma unroll
    for (int n = 0; n < 8; n++) {
        float c0 = acc[n][0] + bf0, c1 = acc[n][1] + bf0;
        float c2 = acc[n][2] + bf1, c3 = acc[n][3] + bf1;
        int gp = pos0 + pw + n*8 + 2*tg;
        *(float2*)(d_y1 + (size_t)r0*PP + gp) = make_float2(c0, c1);
        *(float2*)(d_y1 + (size_t)r1*PP + gp) = make_float2(c2, c3);
        s10 += c0 + c1; s20 += c0*c0 + c1*c1;
        s11 += c2 + c3; s21 += c2*c2 + c3*c3;
    }
#pragma unroll
    for (int off = 1; off <= 2; off <<= 1) {
        s10 += __shfl_xor_sync(0xffffffffu, s10, off);
        s20 += __shfl_xor_sync(0xffffffffu, s20, off);
        s11 += __shfl_xor_sync(0xffffffffu, s11, off);
        s21 += __shfl_xor_sync(0xffffffffu, s21, off);
    }
    if (tg == 0) {
        atomicAdd(&ssum[r0], (double)s10); atomicAdd(&ssq[r0], (double)s20);
        atomicAdd(&ssum[r1], (double)s11); atomicAdd(&ssq[r1], (double)s21);
    }
    __syncthreads();
    if (t < 64) { atomicAdd(&d_sum[128 + t], ssum[t]); atomicAdd(&d_sq[128 + t], ssq[t]); }
}

// ---------------- K7: layer2 tf32-MMA GEMM (64->128) + stats + raw max -----
// Block 128 out x 64 pos (2 rawmax rows). Warp w: out stripe w*16, all 64 pos.
__global__ __launch_bounds__(256, 3) void klast(const float* __restrict__ W,
                      const float* __restrict__ bias,
                      const float* __restrict__ gam,
                      const float* __restrict__ bet) {
    extern __shared__ unsigned smu_[];
    unsigned* sH = smu_;                   // [64][68]
    unsigned* sW = sH + 64*68;             // [128][68]
    float*    smu = (float*)(sW + 128*68); // [64] x4
    float*    srs = smu + 64;
    float*    sga = srs + 64;
    float*    sbe = sga + 64;
    float*    sb  = sbe + 64;              // [128]
    unsigned* smax = (unsigned*)(sb + 128);// [2][128]
    double*   ssum = (double*)(smax + 2*128);
    double*   ssq  = ssum + 128;

    int t = threadIdx.x;
    for (int i = t; i < 128*68; i += 256) {
        int o = i / 68, k = i - o*68;
        sW[o*68 + k] = (k < 64) ? tf32(W[o*64 + k]) : 0u;
    }
    if (t < 64) {
        smu[t] = d_mu[128 + t]; srs[t] = d_rs[128 + t];
        sga[t] = gam[t];        sbe[t] = bet[t];
    }
    if (t < 128) { sb[t] = bias[t]; ssum[t] = 0.0; ssq[t] = 0.0; }
    if (t < 256) { smax[t] = 0u; }
    __syncthreads();

    int pos0 = blockIdx.x * 64;
    for (int i = t; i < 64*16; i += 256) {         // 64 ch x 16 float4
        int c = i >> 4, p4 = i & 15;
        float4 v = *(const float4*)(d_y1 + (size_t)c*PP + pos0 + p4*4);
        float mu = smu[c], rs = srs[c], ga = sga[c], be = sbe[c];
        float a0 = ga*(v.x-mu); a0 *= rs; a0 += be; a0 = fmaxf(a0, 0.f);
        float a1 = ga*(v.y-mu); a1 *= rs; a1 += be; a1 = fmaxf(a1, 0.f);
        float a2 = ga*(v.z-mu); a2 *= rs; a2 += be; a2 = fmaxf(a2, 0.f);
        float a3 = ga*(v.w-mu); a3 *= rs; a3 += be; a3 = fmaxf(a3, 0.f);
        uint4 u; u.x = tf32(a0); u.y = tf32(a1); u.z = tf32(a2); u.w = tf32(a3);
        *(uint4*)(sH + c*68 + p4*4) = u;
    }
    __syncthreads();

    int lane = t & 31, w = t >> 5;
    int g = lane >> 2, tg = lane & 3;
    int out0 = w * 16;

    float acc[8][4];
#pragma unroll
    for (int n = 0; n < 8; n++)
#pragma unroll
        for (int j = 0; j < 4; j++) acc[n][j] = 0.0f;

#pragma unroll
    for (int ks = 0; ks < 8; ks++) {
        int k0 = ks * 8;
        unsigned a0 = sW[(out0+g)*68   + k0 + tg];
        unsigned a1 = sW[(out0+g+8)*68 + k0 + tg];
        unsigned a2 = sW[(out0+g)*68   + k0 + tg + 4];
        unsigned a3 = sW[(out0+g+8)*68 + k0 + tg + 4];
#pragma unroll
        for (int n = 0; n < 8; n++) {
            unsigned b0 = sH[(k0+tg)*68   + n*8 + g];
            unsigned b1 = sH[(k0+tg+4)*68 + n*8 + g];
            mma1688(acc[n][0], acc[n][1], acc[n][2], acc[n][3], a0, a1, a2, a3, b0, b1);
        }
    }

    int r0 = out0 + g, r1 = r0 + 8;
    float bf0 = sb[r0], bf1 = sb[r1];
    float s10 = 0.f, s20 = 0.f, s11 = 0.f, s21 = 0.f;
    float mx00 = -INFINITY, mx01 = -INFINITY;   // r0, windows 0/1
    float mx10 = -INFINITY, mx11 = -INFINITY;   // r1, windows 0/1
#pragma unroll
    for (int n = 0; n < 8; n++) {
        float c0 = acc[n][0] + bf0, c1 = acc[n][1] + bf0;
        float c2 = acc[n][2] + bf1, c3 = acc[n][3] + bf1;
        float p0 = fmaxf(c0, c1), p1 = fmaxf(c2, c3);
        if (n < 4) { mx00 = fmaxf(mx00, p0); mx10 = fmaxf(mx10, p1); }
        else       { mx01 = fmaxf(mx01, p0); mx11 = fmaxf(mx11, p1); }
        s10 += c0 + c1; s20 += c0*c0 + c1*c1;
        s11 += c2 + c3; s21 += c2*c2 + c3*c3;
    }
#pragma unroll
    for (int off = 1; off <= 2; off <<= 1) {
        s10 += __shfl_xor_sync(0xffffffffu, s10, off);
        s20 += __shfl_xor_sync(0xffffffffu, s20, off);
        s11 += __shfl_xor_sync(0xffffffffu, s11, off);
        s21 += __shfl_xor_sync(0xffffffffu, s21, off);
        mx00 = fmaxf(mx00, __shfl_xor_sync(0xffffffffu, mx00, off));
        mx01 = fmaxf(mx01, __shfl_xor_sync(0xffffffffu, mx01, off));
        mx10 = fmaxf(mx10, __shfl_xor_sync(0xffffffffu, mx10, off));
        mx11 = fmaxf(mx11, __shfl_xor_sync(0xffffffffu, mx11, off));
    }
    if (tg == 0) {
        atomicAdd(&ssum[r0], (double)s10); atomicAdd(&ssq[r0], (double)s20);
        atomicAdd(&ssum[r1], (double)s11); atomicAdd(&ssq[r1], (double)s21);
        atomicMax(&smax[0*128 + r0], mkey(mx00));
        atomicMax(&smax[1*128 + r0], mkey(mx01));
        atomicMax(&smax[0*128 + r1], mkey(mx10));
        atomicMax(&smax[1*128 + r1], mkey(mx11));
    }
    __syncthreads();
    if (t < 2*128) {
        int r = (pos0 >> 5) + (t >> 7);
        d_rawmax[(size_t)r*C3 + (t & 127)] = smax[t];
    }
    if (t < 128) { atomicAdd(&d_sum[256 + t], ssum[t]); atomicAdd(&d_sq[256 + t], ssq[t]); }
}

// ---------------- K9: decode raw max, bn2+relu, attention partials ---------
__global__ void kpool(const float* __restrict__ gam, const float* __restrict__ bet) {
    int t = threadIdx.x;
    int c = t & 127, half = t >> 7;
    int blk = blockIdx.x;                  // 256 blocks, 16 per batch
    int b = blk >> 4;
    int r0 = blk * 64 + half * 32;
    float mu = d_mu[256 + c], rs = d_rs[256 + c];
    float ga = gam[c], be = bet[c];
    float sum = 0.0f, mx = 0.0f;
    for (int rr = 0; rr < 32; rr++) {
        int r = r0 + rr;
        float f = unkey(d_rawmax[(size_t)r*C3 + c]);
        float v = ga*(f - mu); v *= rs; v += be; v = fmaxf(v, 0.0f);
        d_np[(size_t)r*C3 + c] = v;
        sum += v; mx = fmaxf(mx, v);
    }
    __shared__ float ssm[256], smm[256];
    ssm[t] = sum; smm[t] = mx;
    __syncthreads();
    if (t < 128) {
        sum = ssm[t] + ssm[t + 128];
        mx = fmaxf(smm[t], smm[t + 128]);
        atomicAdd(&d_avgsum[b*C3 + c], (double)sum);
        atomicMax(&d_maxb[b*C3 + c], __float_as_uint(mx)); // v >= 0
    }
}

// ---------------- K10: channel attention (1 block / batch) -----------------
__global__ void katt(const float* __restrict__ aW1, const float* __restrict__ aW2) {
    int b = blockIdx.x;
    int t = threadIdx.x; // 128
    __shared__ float sav[C3], smx[C3], sha[RR], shm[RR];
    sav[t] = (float)(d_avgsum[b*C3 + t] / (double)SS);
    smx[t] = __uint_as_float(d_maxb[b*C3 + t]);
    __syncthreads();
    if (t < RR) {
        float a = 0.0f, m = 0.0f;
        for (int c = 0; c < C3; c++) {
            a = fmaf(aW1[t*C3 + c], sav[c], a);
            m = fmaf(aW1[t*C3 + c], smx[c], m);
        }
        sha[t] = fmaxf(a, 0.0f);
        shm[t] = fmaxf(m, 0.0f);
    }
    __syncthreads();
    float s1 = 0.0f, s2 = 0.0f;
#pragma unroll
    for (int r = 0; r < RR; r++) {
        s1 = fmaf(aW2[t*RR + r], sha[r], s1);
        s2 = fmaf(aW2[t*RR + r], shm[r], s2);
    }
    float x = s1 + s2;
    d_scale[b*C3 + t] = 1.0f / (1.0f + expf(-x));
}

// ---------------- K11: scale + write new_points ----------------------------
__global__ void kout(float* __restrict__ out) {
    size_t i = (size_t)blockIdx.x * 256 + threadIdx.x;
    if (i < (size_t)BB*SS*C3) {
        int c = (int)(i % C3);
        int r = (int)(i / C3);
        int b = r / SS;
        out[OUT_NP_OFF + i] = d_np[i] * d_scale[b*C3 + c];
    }
}

// ---------------------------------------------------------------------------
extern "C" void kernel_launch(void* const* d_in, const int* in_sizes, int n_in,
                              void* d_out, int out_size) {
    const float* xyz  = (const float*)d_in[0];
    const float* pts  = (const float*)d_in[1];
    const float* W0   = (const float*)d_in[2];
    const float* b0   = (const float*)d_in[3];
    const float* g0   = (const float*)d_in[4];
    const float* be0  = (const float*)d_in[5];
    const float* W1   = (const float*)d_in[6];
    const float* b1   = (const float*)d_in[7];
    const float* g1   = (const float*)d_in[8];
    const float* be1  = (const float*)d_in[9];
    const float* W2   = (const float*)d_in[10];
    const float* b2   = (const float*)d_in[11];
    const float* g2   = (const float*)d_in[12];
    const float* be2  = (const float*)d_in[13];
    const float* aW1  = (const float*)d_in[14];
    const float* aW2  = (const float*)d_in[15];
    float* out = (float*)d_out;

    const int SM_FPS = 3*NPT*4;                                        // 49152
    const int SM_L0  = (72*132 + 64*76)*4 + 64*4 + 64*16;              // 58752
    const int SM_L1  = (64*132 + 64*68)*4 + 5*64*4 + 64*16;            // 53504
    const int SM_L2  = (64*68 + 128*68)*4 + 4*64*4 + 128*4 + 2*128*4 + 128*16; // 56832

    cudaFuncSetAttribute(kfps,    cudaFuncAttributeMaxDynamicSharedMemorySize, SM_FPS);
    cudaFuncSetAttribute(klayer0, cudaFuncAttributeMaxDynamicSharedMemorySize, SM_L0);
    cudaFuncSetAttribute(kmid64,  cudaFuncAttributeMaxDynamicSharedMemorySize, SM_L1);
    cudaFuncSetAttribute(klast,   cudaFuncAttributeMaxDynamicSharedMemorySize, SM_L2);

    kzero<<<8, 256>>>();
    kfps<<<BB, 512, SM_FPS>>>(xyz, out);
    kknn<<<(BB*SS*32)/256, 256>>>(xyz);
    klayer0<<<PP/128, 256, SM_L0>>>(xyz, pts, W0, b0);
    kstats<<<1, 128>>>(0, C1);
    kmid64<<<PP/128, 256, SM_L1>>>(W1, b1, g0, be0);
    kstats<<<1, 128>>>(1, C2);
    klast<<<PP/64, 256, SM_L2>>>(W2, b2, g1, be1);
    kstats<<<1, 128>>>(2, C3);
    kpool<<<256, 256>>>(g2, be2);
    katt<<<BB, 128>>>(aW1, aW2);
    kout<<<(BB*SS*C3 + 255)/256, 256>>>(out);
}

// round 14
// speedup vs baseline: 1.3188x; 1.0914x over previous
#include <cuda_runtime.h>
#include <math.h>

#define BB 16
#define NPT 4096
#define SS 1024
#define KS 32
#define DF 64
#define C0 67
#define C1 64
#define C2 64
#define C3 128
#define RR 16
#define PP (BB*SS*KS)            // 524288 positions

#define OUT_XYZ_OFF 0
#define OUT_NP_OFF  ((size_t)BB*SS*3)
#define OUT_FPS_OFF ((size_t)BB*SS*3 + (size_t)BB*SS*C3)

// ---------------- scratch (static device arrays; no allocs) ----------------
__device__ int      d_fps[BB*SS];
__device__ int      d_knn[BB*SS*KS];
__device__ float    d_y0[(size_t)C1*PP];        // channel-major [c][pos]
__device__ float    d_y1[(size_t)C2*PP];
__device__ unsigned d_rawmax[(size_t)BB*SS*C3]; // per-(row,ch) max of raw y2, keyed
__device__ float    d_np[(size_t)BB*SS*C3];     // pooled, row-major [r][c]
__device__ double   d_sum[3*128];
__device__ double   d_sq[3*128];
__device__ float    d_mu[3*128];
__device__ float    d_rs[3*128];
__device__ double   d_avgsum[BB*C3];
__device__ unsigned d_maxb[BB*C3];
__device__ float    d_scale[BB*C3];

// ---------------- tf32 helpers ---------------------------------------------
__device__ __forceinline__ unsigned tf32(float x) {
    unsigned r;
    asm("cvt.rna.tf32.f32 %0, %1;" : "=r"(r) : "f"(x));
    return r;
}
__device__ __forceinline__ void mma1688(float& c0, float& c1, float& c2, float& c3,
                                        unsigned a0, unsigned a1, unsigned a2, unsigned a3,
                                        unsigned b0, unsigned b1) {
    asm("mma.sync.aligned.m16n8k8.row.col.f32.tf32.tf32.f32 "
        "{%0,%1,%2,%3}, {%4,%5,%6,%7}, {%8,%9}, {%0,%1,%2,%3};"
        : "+f"(c0), "+f"(c1), "+f"(c2), "+f"(c3)
        : "r"(a0), "r"(a1), "r"(a2), "r"(a3), "r"(b0), "r"(b1));
}

// order-preserving float<->uint key (all finite floats)
__device__ __forceinline__ unsigned mkey(float f) {
    unsigned b = __float_as_uint(f);
    return (b & 0x80000000u) ? ~b : (b | 0x80000000u);
}
__device__ __forceinline__ float unkey(unsigned k) {
    unsigned b = (k & 0x80000000u) ? (k & 0x7fffffffu) : ~k;
    return __uint_as_float(b);
}

// ---------------- zero accumulators ----------------------------------------
__global__ void kzero() {
    int t = blockIdx.x * blockDim.x + threadIdx.x;
    if (t < 3*128) { d_sum[t] = 0.0; d_sq[t] = 0.0; }
    if (t < BB*C3) { d_avgsum[t] = 0.0; d_maxb[t] = 0u; }
}

// ---------------- K1: farthest point sampling (1 block / batch) ------------
__global__ __launch_bounds__(512) void kfps(const float* __restrict__ xyz, float* __restrict__ out) {
    int b = blockIdx.x;
    extern __shared__ float sh[];
    float* sx = sh;
    float* sy = sh + NPT;
    float* sz = sh + 2*NPT;
    __shared__ unsigned rb[2][16];
    __shared__ int      ri[2][16];

    int t = threadIdx.x;
    int lane = t & 31, wid = t >> 5;
    const float* xb = xyz + (size_t)b * NPT * 3;
    for (int p = t; p < NPT; p += 512) {
        sx[p] = xb[3*p]; sy[p] = xb[3*p+1]; sz[p] = xb[3*p+2];
    }
    __syncthreads();

    float px[8], py[8], pz[8], dist[8];
#pragma unroll
    for (int j = 0; j < 8; j++) {
        int p = j*512 + t;
        px[j] = sx[p]; py[j] = sy[p]; pz[j] = sz[p];
        dist[j] = INFINITY;
    }

    int far = NPT / 2;
    int ph = 0;
    for (int i = 0; i < SS; i++) {
        if (t == 0) {
            d_fps[b*SS + i] = far;
            out[OUT_XYZ_OFF + (size_t)(b*SS + i)*3 + 0] = sx[far];
            out[OUT_XYZ_OFF + (size_t)(b*SS + i)*3 + 1] = sy[far];
            out[OUT_XYZ_OFF + (size_t)(b*SS + i)*3 + 2] = sz[far];
            out[OUT_FPS_OFF + b*SS + i] = (float)far;
        }
        if (i == SS - 1) break;   // last centroid's successor is never used
        float cx = sx[far], cy = sy[far], cz = sz[far];
        float bv = -1.0f; int bi = 0;
#pragma unroll
        for (int j = 0; j < 8; j++) {
            float dx = __fadd_rn(px[j], -cx);
            float dy = __fadd_rn(py[j], -cy);
            float dz = __fadd_rn(pz[j], -cz);
            float d = __fadd_rn(__fadd_rn(__fmul_rn(dx,dx), __fmul_rn(dy,dy)),
                                __fmul_rn(dz,dz));
            float nd = fminf(dist[j], d);
            dist[j] = nd;
            if (nd > bv) { bv = nd; bi = j*512 + t; }  // lowest idx kept on tie
        }
        unsigned db = __float_as_uint(bv);
        unsigned m  = __reduce_max_sync(0xffffffffu, db);
        unsigned ii = (db == m) ? (unsigned)bi : 0xffffffffu;
        unsigned wi = __reduce_min_sync(0xffffffffu, ii);
        if (lane == 0) { rb[ph][wid] = m; ri[ph][wid] = (int)wi; }
        __syncthreads();
        unsigned m2 = (lane < 16) ? rb[ph][lane] : 0u;
        unsigned mm = __reduce_max_sync(0xffffffffu, m2);
        unsigned i2 = (lane < 16 && m2 == mm) ? (unsigned)ri[ph][lane] : 0xffffffffu;
        far = (int)__reduce_min_sync(0xffffffffu, i2);
        ph ^= 1;
    }
}

// ---------------- K2: 32-NN per sampled point (warp per query) -------------
__global__ void kknn(const float* __restrict__ xyz) {
    int warp = (blockIdx.x * blockDim.x + threadIdx.x) >> 5;
    int lane = threadIdx.x & 31;
    if (warp >= BB*SS) return;
    int b = warp / SS;
    int qi = d_fps[warp];
    const float* xb = xyz + (size_t)b * NPT * 3;
    float qx = xb[3*qi], qy = xb[3*qi+1], qz = xb[3*qi+2];
    float ss2 = qx*qx + qy*qy + qz*qz;

    auto distf = [&](int n) {
        float x = xb[3*n], y = xb[3*n+1], z = xb[3*n+2];
        float dot = x*qx + y*qy + z*qz;
        float nn2 = x*x + y*y + z*z;
        return -2.0f*dot + ss2 + nn2;
    };

    float hd = distf(lane);
    int   hi = lane;
    float md; int mi, ml;
    auto worst32 = [&]() {
        unsigned key = __float_as_uint(hd);       // dists >= 0
        unsigned m = __reduce_max_sync(0xffffffffu, key);
        unsigned im = __reduce_max_sync(0xffffffffu,
                          (key == m) ? (unsigned)hi : 0u);
        unsigned lm = __ballot_sync(0xffffffffu,
                          (key == m) && ((unsigned)hi == im));
        md = __uint_as_float(m);
        mi = (int)im;
        ml = 31 - __clz(lm);
    };
    worst32();

    for (int it = 1; it < NPT/32; it++) {
        int n = it*32 + lane;
        float dc = distf(n);
        bool pr = (dc < md) || (dc == md && n < mi);
        unsigned mask = __ballot_sync(0xffffffffu, pr);
        while (mask) {
            int l = __ffs(mask) - 1; mask &= mask - 1;
            float cd = __shfl_sync(0xffffffffu, dc, l);
            int   ci = it*32 + l;
            if (cd < md || (cd == md && ci < mi)) {
                if (lane == ml) { hd = cd; hi = ci; }
                worst32();
            }
        }
    }
    d_knn[warp*KS + lane] = hi;
}

// ---------------- K3: gather + layer0 tf32-MMA GEMM + stats ----------------
// Block: 64 out x 256 pos, 512 thr = 16 warps (4 out-stripes x 4 pos-windows).
// W smem [64][76] (A-frag banks 12g+tg, CF). H smem [72][260] (260 mod 32 = 4,
// B-frag banks 4tg+g, CF); k rows 67..71 zero.
__global__ __launch_bounds__(512, 2) void klayer0(const float* __restrict__ xyz,
                        const float* __restrict__ pts,
                        const float* __restrict__ W,
                        const float* __restrict__ bias) {
    extern __shared__ unsigned smu_[];
    unsigned* sH = smu_;                 // [72][260]
    unsigned* sW = sH + 72*260;          // [64][76]
    float*    sb = (float*)(sW + 64*76); // [64]
    double*   ssum = (double*)(sb + 64);
    double*   ssq  = ssum + 64;

    int t = threadIdx.x;
    for (int i = t; i < 64*72; i += 512) {
        int o = i / 72, k = i - o*72;
        sW[o*76 + k] = (k < C0) ? tf32(W[o*C0 + k]) : 0u;
    }
    if (t < 64) { sb[t] = bias[t]; ssum[t] = 0.0; ssq[t] = 0.0; }
    for (int i = t; i < 5*260; i += 512)
        sH[(67 + i/260)*260 + (i % 260)] = 0u;

    int pos0 = blockIdx.x * 256;
    {   // gather: 2 threads per position
        int p = t >> 1, half = t & 1;
        int pos = pos0 + p;
        int n  = d_knn[pos];
        int b  = pos >> 15;
        const float* pbase = pts + ((size_t)b*NPT + n) * DF;
        if (half == 0) {
            int qi = d_fps[pos >> 5];
            const float* xb = xyz + (size_t)b * NPT * 3;
            sH[0*260 + p] = tf32(xb[3*n]   - xb[3*qi]);
            sH[1*260 + p] = tf32(xb[3*n+1] - xb[3*qi+1]);
            sH[2*260 + p] = tf32(xb[3*n+2] - xb[3*qi+2]);
        }
        const float4* pb = (const float4*)pbase;
#pragma unroll
        for (int c4 = half*8; c4 < half*8 + 8; c4++) {
            float4 v = pb[c4];
            sH[(3+4*c4+0)*260 + p] = tf32(v.x);
            sH[(3+4*c4+1)*260 + p] = tf32(v.y);
            sH[(3+4*c4+2)*260 + p] = tf32(v.z);
            sH[(3+4*c4+3)*260 + p] = tf32(v.w);
        }
    }
    __syncthreads();

    int lane = t & 31, w = t >> 5;
    int g = lane >> 2, tg = lane & 3;
    int out0 = (w & 3) * 16;
    int pw   = (w >> 2) * 64;

    float acc[8][4];
#pragma unroll
    for (int n = 0; n < 8; n++)
#pragma unroll
        for (int j = 0; j < 4; j++) acc[n][j] = 0.0f;

#pragma unroll
    for (int ks = 0; ks < 9; ks++) {
        int k0 = ks * 8;
        unsigned a0 = sW[(out0+g)*76   + k0 + tg];
        unsigned a1 = sW[(out0+g+8)*76 + k0 + tg];
        unsigned a2 = sW[(out0+g)*76   + k0 + tg + 4];
        unsigned a3 = sW[(out0+g+8)*76 + k0 + tg + 4];
#pragma unroll
        for (int n = 0; n < 8; n++) {
            unsigned b0 = sH[(k0+tg)*260   + pw + n*8 + g];
            unsigned b1 = sH[(k0+tg+4)*260 + pw + n*8 + g];
            mma1688(acc[n][0], acc[n][1], acc[n][2], acc[n][3], a0, a1, a2, a3, b0, b1);
        }
    }

    int r0 = out0 + g, r1 = r0 + 8;
    float bf0 = sb[r0], bf1 = sb[r1];
    float s10 = 0.f, s20 = 0.f, s11 = 0.f, s21 = 0.f;
#pragma unroll
    for (int n = 0; n < 8; n++) {
        float c0 = acc[n][0] + bf0, c1 = acc[n][1] + bf0;
        float c2 = acc[n][2] + bf1, c3 = acc[n][3] + bf1;
        int gp = pos0 + pw + n*8 + 2*tg;
        *(float2*)(d_y0 + (size_t)r0*PP + gp) = make_float2(c0, c1);
        *(float2*)(d_y0 + (size_t)r1*PP + gp) = make_float2(c2, c3);
        s10 += c0 + c1; s20 += c0*c0 + c1*c1;
        s11 += c2 + c3; s21 += c2*c2 + c3*c3;
    }
#pragma unroll
    for (int off = 1; off <= 2; off <<= 1) {
        s10 += __shfl_xor_sync(0xffffffffu, s10, off);
        s20 += __shfl_xor_sync(0xffffffffu, s20, off);
        s11 += __shfl_xor_sync(0xffffffffu, s11, off);
        s21 += __shfl_xor_sync(0xffffffffu, s21, off);
    }
    if (tg == 0) {
        atomicAdd(&ssum[r0], (double)s10); atomicAdd(&ssq[r0], (double)s20);
        atomicAdd(&ssum[r1], (double)s11); atomicAdd(&ssq[r1], (double)s21);
    }
    __syncthreads();
    if (t < 64) { atomicAdd(&d_sum[t], ssum[t]); atomicAdd(&d_sq[t], ssq[t]); }
}

// ---------------- finalize BN stats ----------------------------------------
__global__ void kstats(int L, int C) {
    int c = threadIdx.x;
    if (c < C) {
        double cnt = (double)PP;
        double mu  = d_sum[L*128 + c] / cnt;
        double var = d_sq[L*128 + c] / cnt - mu*mu;
        d_mu[L*128 + c] = (float)mu;
        d_rs[L*128 + c] = (float)(1.0 / sqrt(var + 1e-5));
    }
}

// ---------------- K5: layer1 tf32-MMA GEMM (64->64), bn0+relu on load ------
// Block 64 out x 256 pos, 512 thr. W smem [64][68] (float4-staged), H [64][260].
__global__ __launch_bounds__(512, 2) void kmid64(const float* __restrict__ W,
                       const float* __restrict__ bias,
                       const float* __restrict__ gam,
                       const float* __restrict__ bet) {
    extern __shared__ unsigned smu_[];
    unsigned* sH = smu_;                  // [64][260]
    unsigned* sW = sH + 64*260;           // [64][68]
    float*    smu = (float*)(sW + 64*68); // [64] x4
    float*    srs = smu + 64;
    float*    sga = srs + 64;
    float*    sbe = sga + 64;
    float*    sb  = sbe + 64;
    double*   ssum = (double*)(sb + 64);
    double*   ssq  = ssum + 64;

    int t = threadIdx.x;
    for (int i = t; i < 64*16; i += 512) {         // float4 W staging
        int o = i >> 4, k4 = i & 15;
        float4 v = *(const float4*)(W + o*64 + k4*4);
        uint4 u; u.x = tf32(v.x); u.y = tf32(v.y); u.z = tf32(v.z); u.w = tf32(v.w);
        *(uint4*)(sW + o*68 + k4*4) = u;
    }
    if (t < 64) {
        sW[t*68 + 64] = 0u; sW[t*68 + 65] = 0u; sW[t*68 + 66] = 0u; sW[t*68 + 67] = 0u;
        smu[t] = d_mu[t]; srs[t] = d_rs[t];
        sga[t] = gam[t];  sbe[t] = bet[t];
        sb[t] = bias[t]; ssum[t] = 0.0; ssq[t] = 0.0;
    }
    __syncthreads();

    int pos0 = blockIdx.x * 256;
    for (int i = t; i < 64*64; i += 512) {        // 64 ch x 64 float4 (256 pos)
        int c = i >> 6, p4 = i & 63;
        float4 v = *(const float4*)(d_y0 + (size_t)c*PP + pos0 + p4*4);
        float mu = smu[c], rs = srs[c], ga = sga[c], be = sbe[c];
        float a0 = ga*(v.x-mu); a0 *= rs; a0 += be; a0 = fmaxf(a0, 0.f);
        float a1 = ga*(v.y-mu); a1 *= rs; a1 += be; a1 = fmaxf(a1, 0.f);
        float a2 = ga*(v.z-mu); a2 *= rs; a2 += be; a2 = fmaxf(a2, 0.f);
        float a3 = ga*(v.w-mu); a3 *= rs; a3 += be; a3 = fmaxf(a3, 0.f);
        uint4 u; u.x = tf32(a0); u.y = tf32(a1); u.z = tf32(a2); u.w = tf32(a3);
        *(uint4*)(sH + c*260 + p4*4) = u;
    }
    __syncthreads();

    int lane = t & 31, w = t >> 5;
    int g = lane >> 2, tg = lane & 3;
    int out0 = (w & 3) * 16;
    int pw   = (w >> 2) * 64;

    float acc[8][4];
#pragma unroll
    for (int n = 0; n < 8; n++)
#pragma unroll
        for (int j = 0; j < 4; j++) acc[n][j] = 0.0f;

#pragma unroll
    for (int ks = 0; ks < 8; ks++) {
        int k0 = ks * 8;
        unsigned a0 = sW[(out0+g)*68   + k0 + tg];
        unsigned a1 = sW[(out0+g+8)*68 + k0 + tg];
        unsigned a2 = sW[(out0+g)*68   + k0 + tg + 4];
        unsigned a3 = sW[(out0+g+8)*68 + k0 + tg + 4];
#pragma unroll
        for (int n = 0; n < 8; n++) {
            unsigned b0 = sH[(k0+tg)*260   + pw + n*8 + g];
            unsigned b1 = sH[(k0+tg+4)*260 + pw + n*8 + g];
            mma1688(acc[n][0], acc[n][1], acc[n][2], acc[n][3], a0, a1, a2, a3, b0, b1);
        }
    }

    int r0 = out0 + g, r1 = r0 + 8;
    float bf0 = sb[r0], bf1 = sb[r1];
    float s10 = 0.f, s20 = 0.f, s11 = 0.f, s21 = 0.f;
#pragma unroll
    for (int n = 0; n < 8; n++) {
        float c0 = acc[n][0] + bf0, c1 = acc[n][1] + bf0;
        float c2 = acc[n][2] + bf1, c3 = acc[n][3] + bf1;
        int gp = pos0 + pw + n*8 + 2*tg;
        *(float2*)(d_y1 + (size_t)r0*PP + gp) = make_float2(c0, c1);
        *(float2*)(d_y1 + (size_t)r1*PP + gp) = make_float2(c2, c3);
        s10 += c0 + c1; s20 += c0*c0 + c1*c1;
        s11 += c2 + c3; s21 += c2*c2 + c3*c3;
    }
#pragma unroll
    for (int off = 1; off <= 2; off <<= 1) {
        s10 += __shfl_xor_sync(0xffffffffu, s10, off);
        s20 += __shfl_xor_sync(0xffffffffu, s20, off);
        s11 += __shfl_xor_sync(0xffffffffu, s11, off);
        s21 += __shfl_xor_sync(0xffffffffu, s21, off);
    }
    if (tg == 0) {
        atomicAdd(&ssum[r0], (double)s10); atomicAdd(&ssq[r0], (double)s20);
        atomicAdd(&ssum[r1], (double)s11); atomicAdd(&ssq[r1], (double)s21);
    }
    __syncthreads();
    if (t < 64) { atomicAdd(&d_sum[128 + t], ssum[t]); atomicAdd(&d_sq[128 + t], ssq[t]); }
}

// ---------------- K7: layer2 tf32-MMA GEMM (64->128) + stats + raw max -----
// Block 128 out x 128 pos, 512 thr = 16 warps (8 out-stripes x 2 pos-windows).
__global__ __launch_bounds__(512, 3) void klast(const float* __restrict__ W,
                      const float* __restrict__ bias,
                      const float* __restrict__ gam,
                      const float* __restrict__ bet) {
    extern __shared__ unsigned smu_[];
    unsigned* sH = smu_;                   // [64][132]
    unsigned* sW = sH + 64*132;            // [128][68]
    float*    smu = (float*)(sW + 128*68); // [64] x4
    float*    srs = smu + 64;
    float*    sga = srs + 64;
    float*    sbe = sga + 64;
    float*    sb  = sbe + 64;              // [128]
    unsigned* smax = (unsigned*)(sb + 128);// [4][128]
    double*   ssum = (double*)(smax + 4*128);
    double*   ssq  = ssum + 128;

    int t = threadIdx.x;
    for (int i = t; i < 128*16; i += 512) {        // float4 W staging
        int o = i >> 4, k4 = i & 15;
        float4 v = *(const float4*)(W + o*64 + k4*4);
        uint4 u; u.x = tf32(v.x); u.y = tf32(v.y); u.z = tf32(v.z); u.w = tf32(v.w);
        *(uint4*)(sW + o*68 + k4*4) = u;
    }
    if (t < 128) {
        sW[t*68 + 64] = 0u; sW[t*68 + 65] = 0u; sW[t*68 + 66] = 0u; sW[t*68 + 67] = 0u;
        sb[t] = bias[t]; ssum[t] = 0.0; ssq[t] = 0.0;
    }
    if (t < 64) {
        smu[t] = d_mu[128 + t]; srs[t] = d_rs[128 + t];
        sga[t] = gam[t];        sbe[t] = bet[t];
    }
    smax[t] = 0u;                                   // 512 = 4*128
    __syncthreads();

    int pos0 = blockIdx.x * 128;
    for (int i = t; i < 64*32; i += 512) {         // 64 ch x 32 float4 (128 pos)
        int c = i >> 5, p4 = i & 31;
        float4 v = *(const float4*)(d_y1 + (size_t)c*PP + pos0 + p4*4);
        float mu = smu[c], rs = srs[c], ga = sga[c], be = sbe[c];
        float a0 = ga*(v.x-mu); a0 *= rs; a0 += be; a0 = fmaxf(a0, 0.f);
        float a1 = ga*(v.y-mu); a1 *= rs; a1 += be; a1 = fmaxf(a1, 0.f);
        float a2 = ga*(v.z-mu); a2 *= rs; a2 += be; a2 = fmaxf(a2, 0.f);
        float a3 = ga*(v.w-mu); a3 *= rs; a3 += be; a3 = fmaxf(a3, 0.f);
        uint4 u; u.x = tf32(a0); u.y = tf32(a1); u.z = tf32(a2); u.w = tf32(a3);
        *(uint4*)(sH + c*132 + p4*4) = u;
    }
    __syncthreads();

    int lane = t & 31, w = t >> 5;
    int g = lane >> 2, tg = lane & 3;
    int out0 = (w & 7) * 16;
    int pw   = (w >> 3) * 64;

    float acc[8][4];
#pragma unroll
    for (int n = 0; n < 8; n++)
#pragma unroll
        for (int j = 0; j < 4; j++) acc[n][j] = 0.0f;

#pragma unroll
    for (int ks = 0; ks < 8; ks++) {
        int k0 = ks * 8;
        unsigned a0 = sW[(out0+g)*68   + k0 + tg];
        unsigned a1 = sW[(out0+g+8)*68 + k0 + tg];
        unsigned a2 = sW[(out0+g)*68   + k0 + tg + 4];
        unsigned a3 = sW[(out0+g+8)*68 + k0 + tg + 4];
#pragma unroll
        for (int n = 0; n < 8; n++) {
            unsigned b0 = sH[(k0+tg)*132   + pw + n*8 + g];
            unsigned b1 = sH[(k0+tg+4)*132 + pw + n*8 + g];
            mma1688(acc[n][0], acc[n][1], acc[n][2], acc[n][3], a0, a1, a2, a3, b0, b1);
        }
    }

    int r0 = out0 + g, r1 = r0 + 8;
    float bf0 = sb[r0], bf1 = sb[r1];
    float s10 = 0.f, s20 = 0.f, s11 = 0.f, s21 = 0.f;
    float mx00 = -INFINITY, mx01 = -INFINITY;   // r0, windows pw/32, pw/32+1
    float mx10 = -INFINITY, mx11 = -INFINITY;   // r1
#pragma unroll
    for (int n = 0; n < 8; n++) {
        float c0 = acc[n][0] + bf0, c1 = acc[n][1] + bf0;
        float c2 = acc[n][2] + bf1, c3 = acc[n][3] + bf1;
        float p0 = fmaxf(c0, c1), p1 = fmaxf(c2, c3);
        if (n < 4) { mx00 = fmaxf(mx00, p0); mx10 = fmaxf(mx10, p1); }
        else       { mx01 = fmaxf(mx01, p0); mx11 = fmaxf(mx11, p1); }
        s10 += c0 + c1; s20 += c0*c0 + c1*c1;
        s11 += c2 + c3; s21 += c2*c2 + c3*c3;
    }
#pragma unroll
    for (int off = 1; off <= 2; off <<= 1) {
        s10 += __shfl_xor_sync(0xffffffffu, s10, off);
        s20 += __shfl_xor_sync(0xffffffffu, s20, off);
        s11 += __shfl_xor_sync(0xffffffffu, s11, off);
        s21 += __shfl_xor_sync(0xffffffffu, s21, off);
        mx00 = fmaxf(mx00, __shfl_xor_sync(0xffffffffu, mx00, off));
        mx01 = fmaxf(mx01, __shfl_xor_sync(0xffffffffu, mx01, off));
        mx10 = fmaxf(mx10, __shfl_xor_sync(0xffffffffu, mx10, off));
        mx11 = fmaxf(mx11, __shfl_xor_sync(0xffffffffu, mx11, off));
    }
    if (tg == 0) {
        int wb = (pw >> 5);   // 0 or 2
        atomicAdd(&ssum[r0], (double)s10); atomicAdd(&ssq[r0], (double)s20);
        atomicAdd(&ssum[r1], (double)s11); atomicAdd(&ssq[r1], (double)s21);
        atomicMax(&smax[(wb  )*128 + r0], mkey(mx00));
        atomicMax(&smax[(wb+1)*128 + r0], mkey(mx01));
        atomicMax(&smax[(wb  )*128 + r1], mkey(mx10));
        atomicMax(&smax[(wb+1)*128 + r1], mkey(mx11));
    }
    __syncthreads();
    {
        int r = (pos0 >> 5) + (t >> 7);            // 4 windows
        d_rawmax[(size_t)r*C3 + (t & 127)] = smax[t];
    }
    if (t < 128) { atomicAdd(&d_sum[256 + t], ssum[t]); atomicAdd(&d_sq[256 + t], ssq[t]); }
}

// ---------------- K9: decode raw max, bn2+relu, attention partials ---------
__global__ void kpool(const float* __restrict__ gam, const float* __restrict__ bet) {
    int t = threadIdx.x;
    int c = t & 127, half = t >> 7;
    int blk = blockIdx.x;                  // 256 blocks, 16 per batch
    int b = blk >> 4;
    int r0 = blk * 64 + half * 32;
    float mu = d_mu[256 + c], rs = d_rs[256 + c];
    float ga = gam[c], be = bet[c];
    float sum = 0.0f, mx = 0.0f;
    for (int rr = 0; rr < 32; rr++) {
        int r = r0 + rr;
        float f = unkey(d_rawmax[(size_t)r*C3 + c]);
        float v = ga*(f - mu); v *= rs; v += be; v = fmaxf(v, 0.0f);
        d_np[(size_t)r*C3 + c] = v;
        sum += v; mx = fmaxf(mx, v);
    }
    __shared__ float ssm[256], smm[256];
    ssm[t] = sum; smm[t] = mx;
    __syncthreads();
    if (t < 128) {
        sum = ssm[t] + ssm[t + 128];
        mx = fmaxf(smm[t], smm[t + 128]);
        atomicAdd(&d_avgsum[b*C3 + c], (double)sum);
        atomicMax(&d_maxb[b*C3 + c], __float_as_uint(mx)); // v >= 0
    }
}

// ---------------- K10: channel attention (1 block / batch) -----------------
__global__ void katt(const float* __restrict__ aW1, const float* __restrict__ aW2) {
    int b = blockIdx.x;
    int t = threadIdx.x; // 128
    __shared__ float sav[C3], smx[C3], sha[RR], shm[RR];
    sav[t] = (float)(d_avgsum[b*C3 + t] / (double)SS);
    smx[t] = __uint_as_float(d_maxb[b*C3 + t]);
    __syncthreads();
    if (t < RR) {
        float a = 0.0f, m = 0.0f;
        for (int c = 0; c < C3; c++) {
            a = fmaf(aW1[t*C3 + c], sav[c], a);
            m = fmaf(aW1[t*C3 + c], smx[c], m);
        }
        sha[t] = fmaxf(a, 0.0f);
        shm[t] = fmaxf(m, 0.0f);
    }
    __syncthreads();
    float s1 = 0.0f, s2 = 0.0f;
#pragma unroll
    for (int r = 0; r < RR; r++) {
        s1 = fmaf(aW2[t*RR + r], sha[r], s1);
        s2 = fmaf(aW2[t*RR + r], shm[r], s2);
    }
    float x = s1 + s2;
    d_scale[b*C3 + t] = 1.0f / (1.0f + expf(-x));
}

// ---------------- K11: scale + write new_points ----------------------------
__global__ void kout(float* __restrict__ out) {
    size_t i = (size_t)blockIdx.x * 256 + threadIdx.x;
    if (i < (size_t)BB*SS*C3) {
        int c = (int)(i % C3);
        int r = (int)(i / C3);
        int b = r / SS;
        out[OUT_NP_OFF + i] = d_np[i] * d_scale[b*C3 + c];
    }
}

// ---------------------------------------------------------------------------
extern "C" void kernel_launch(void* const* d_in, const int* in_sizes, int n_in,
                              void* d_out, int out_size) {
    const float* xyz  = (const float*)d_in[0];
    const float* pts  = (const float*)d_in[1];
    const float* W0   = (const float*)d_in[2];
    const float* b0   = (const float*)d_in[3];
    const float* g0   = (const float*)d_in[4];
    const float* be0  = (const float*)d_in[5];
    const float* W1   = (const float*)d_in[6];
    const float* b1   = (const float*)d_in[7];
    const float* g1   = (const float*)d_in[8];
    const float* be1  = (const float*)d_in[9];
    const float* W2   = (const float*)d_in[10];
    const float* b2   = (const float*)d_in[11];
    const float* g2   = (const float*)d_in[12];
    const float* be2  = (const float*)d_in[13];
    const float* aW1  = (const float*)d_in[14];
    const float* aW2  = (const float*)d_in[15];
    float* out = (float*)d_out;

    const int SM_FPS = 3*NPT*4;                                        // 49152
    const int SM_L0  = (72*260 + 64*76)*4 + 64*4 + 64*16;              // 95616
    const int SM_L1  = (64*260 + 64*68)*4 + 5*64*4 + 64*16;            // 86272
    const int SM_L2  = (64*132 + 128*68)*4 + 4*64*4 + 128*4 + 4*128*4 + 128*16; // 75264

    cudaFuncSetAttribute(kfps,    cudaFuncAttributeMaxDynamicSharedMemorySize, SM_FPS);
    cudaFuncSetAttribute(klayer0, cudaFuncAttributeMaxDynamicSharedMemorySize, SM_L0);
    cudaFuncSetAttribute(kmid64,  cudaFuncAttributeMaxDynamicSharedMemorySize, SM_L1);
    cudaFuncSetAttribute(klast,   cudaFuncAttributeMaxDynamicSharedMemorySize, SM_L2);

    kzero<<<8, 256>>>();
    kfps<<<BB, 512, SM_FPS>>>(xyz, out);
    kknn<<<(BB*SS*32)/256, 256>>>(xyz);
    klayer0<<<PP/256, 512, SM_L0>>>(xyz, pts, W0, b0);
    kstats<<<1, 128>>>(0, C1);
    kmid64<<<PP/256, 512, SM_L1>>>(W1, b1, g0, be0);
    kstats<<<1, 128>>>(1, C2);
    klast<<<PP/128, 512, SM_L2>>>(W2, b2, g1, be1);
    kstats<<<1, 128>>>(2, C3);
    kpool<<<256, 256>>>(g2, be2);
    katt<<<BB, 128>>>(aW1, aW2);
    kout<<<(BB*SS*C3 + 255)/256, 256>>>(out);
}

// round 16
// speedup vs baseline: 1.3764x; 1.0437x over previous
#include <cuda_runtime.h>
#include <math.h>

#define BB 16
#define NPT 4096
#define SS 1024
#define KS 32
#define DF 64
#define C0 67
#define C1 64
#define C2 64
#define C3 128
#define RR 16
#define PP (BB*SS*KS)            // 524288 positions

#define OUT_XYZ_OFF 0
#define OUT_NP_OFF  ((size_t)BB*SS*3)
#define OUT_FPS_OFF ((size_t)BB*SS*3 + (size_t)BB*SS*C3)

// ---------------- scratch (static device arrays; no allocs) ----------------
__device__ int      d_fps[BB*SS];
__device__ int      d_knn[BB*SS*KS];
__device__ float    d_y0[(size_t)C1*PP];        // channel-major [c][pos]
__device__ float    d_y1[(size_t)C2*PP];
__device__ unsigned d_rawmax[(size_t)BB*SS*C3]; // per-(row,ch) max of raw y2, keyed
__device__ float    d_np[(size_t)BB*SS*C3];     // pooled, row-major [r][c]
__device__ double   d_sum[3*128];
__device__ double   d_sq[3*128];
__device__ float    d_mu[3*128];
__device__ float    d_rs[3*128];
__device__ double   d_avgsum[BB*C3];
__device__ unsigned d_maxb[BB*C3];
__device__ float    d_scale[BB*C3];

// ---------------- tf32 helpers ---------------------------------------------
__device__ __forceinline__ unsigned tf32(float x) {
    unsigned r;
    asm("cvt.rna.tf32.f32 %0, %1;" : "=r"(r) : "f"(x));
    return r;
}
__device__ __forceinline__ void mma1688(float& c0, float& c1, float& c2, float& c3,
                                        unsigned a0, unsigned a1, unsigned a2, unsigned a3,
                                        unsigned b0, unsigned b1) {
    asm("mma.sync.aligned.m16n8k8.row.col.f32.tf32.tf32.f32 "
        "{%0,%1,%2,%3}, {%4,%5,%6,%7}, {%8,%9}, {%0,%1,%2,%3};"
        : "+f"(c0), "+f"(c1), "+f"(c2), "+f"(c3)
        : "r"(a0), "r"(a1), "r"(a2), "r"(a3), "r"(b0), "r"(b1));
}

// order-preserving float<->uint key (all finite floats)
__device__ __forceinline__ unsigned mkey(float f) {
    unsigned b = __float_as_uint(f);
    return (b & 0x80000000u) ? ~b : (b | 0x80000000u);
}
__device__ __forceinline__ float unkey(unsigned k) {
    unsigned b = (k & 0x80000000u) ? (k & 0x7fffffffu) : ~k;
    return __uint_as_float(b);
}

// ---------------- zero accumulators ----------------------------------------
__global__ void kzero() {
    int t = blockIdx.x * blockDim.x + threadIdx.x;
    if (t < 3*128) { d_sum[t] = 0.0; d_sq[t] = 0.0; }
    if (t < BB*C3) { d_avgsum[t] = 0.0; d_maxb[t] = 0u; }
}

// ---------------- K1: farthest point sampling (1 block / batch) ------------
__global__ __launch_bounds__(512) void kfps(const float* __restrict__ xyz, float* __restrict__ out) {
    int b = blockIdx.x;
    extern __shared__ float sh[];
    float* sx = sh;
    float* sy = sh + NPT;
    float* sz = sh + 2*NPT;
    __shared__ unsigned rb[2][16];
    __shared__ int      ri[2][16];

    int t = threadIdx.x;
    int lane = t & 31, wid = t >> 5;
    const float* xb = xyz + (size_t)b * NPT * 3;
    for (int p = t; p < NPT; p += 512) {
        sx[p] = xb[3*p]; sy[p] = xb[3*p+1]; sz[p] = xb[3*p+2];
    }
    __syncthreads();

    float px[8], py[8], pz[8], dist[8];
#pragma unroll
    for (int j = 0; j < 8; j++) {
        int p = j*512 + t;
        px[j] = sx[p]; py[j] = sy[p]; pz[j] = sz[p];
        dist[j] = INFINITY;
    }

    int far = NPT / 2;
    int ph = 0;
    for (int i = 0; i < SS; i++) {
        if (t == 0) {
            d_fps[b*SS + i] = far;
            out[OUT_XYZ_OFF + (size_t)(b*SS + i)*3 + 0] = sx[far];
            out[OUT_XYZ_OFF + (size_t)(b*SS + i)*3 + 1] = sy[far];
            out[OUT_XYZ_OFF + (size_t)(b*SS + i)*3 + 2] = sz[far];
            out[OUT_FPS_OFF + b*SS + i] = (float)far;
        }
        if (i == SS - 1) break;   // last centroid's successor is never used
        float cx = sx[far], cy = sy[far], cz = sz[far];
        float bv = -1.0f; int bi = 0;
#pragma unroll
        for (int j = 0; j < 8; j++) {
            float dx = __fadd_rn(px[j], -cx);
            float dy = __fadd_rn(py[j], -cy);
            float dz = __fadd_rn(pz[j], -cz);
            float d = __fadd_rn(__fadd_rn(__fmul_rn(dx,dx), __fmul_rn(dy,dy)),
                                __fmul_rn(dz,dz));
            float nd = fminf(dist[j], d);
            dist[j] = nd;
            if (nd > bv) { bv = nd; bi = j*512 + t; }  // lowest idx kept on tie
        }
        unsigned db = __float_as_uint(bv);
        unsigned m  = __reduce_max_sync(0xffffffffu, db);
        unsigned ii = (db == m) ? (unsigned)bi : 0xffffffffu;
        unsigned wi = __reduce_min_sync(0xffffffffu, ii);
        if (lane == 0) { rb[ph][wid] = m; ri[ph][wid] = (int)wi; }
        __syncthreads();
        unsigned m2 = (lane < 16) ? rb[ph][lane] : 0u;
        unsigned mm = __reduce_max_sync(0xffffffffu, m2);
        unsigned i2 = (lane < 16 && m2 == mm) ? (unsigned)ri[ph][lane] : 0xffffffffu;
        far = (int)__reduce_min_sync(0xffffffffu, i2);
        ph ^= 1;
    }
}

// ---------------- K2: 32-NN per sampled point (warp per query) -------------
__global__ void kknn(const float* __restrict__ xyz) {
    int warp = (blockIdx.x * blockDim.x + threadIdx.x) >> 5;
    int lane = threadIdx.x & 31;
    if (warp >= BB*SS) return;
    int b = warp / SS;
    int qi = d_fps[warp];
    const float* xb = xyz + (size_t)b * NPT * 3;
    float qx = xb[3*qi], qy = xb[3*qi+1], qz = xb[3*qi+2];
    float ss2 = qx*qx + qy*qy + qz*qz;

    auto distf = [&](int n) {
        float x = xb[3*n], y = xb[3*n+1], z = xb[3*n+2];
        float dot = x*qx + y*qy + z*qz;
        float nn2 = x*x + y*y + z*z;
        return -2.0f*dot + ss2 + nn2;
    };

    float hd = distf(lane);
    int   hi = lane;
    float md; int mi, ml;
    auto worst32 = [&]() {
        unsigned key = __float_as_uint(hd);       // dists >= 0
        unsigned m = __reduce_max_sync(0xffffffffu, key);
        unsigned im = __reduce_max_sync(0xffffffffu,
                          (key == m) ? (unsigned)hi : 0u);
        unsigned lm = __ballot_sync(0xffffffffu,
                          (key == m) && ((unsigned)hi == im));
        md = __uint_as_float(m);
        mi = (int)im;
        ml = 31 - __clz(lm);
    };
    worst32();

    for (int it = 1; it < NPT/32; it++) {
        int n = it*32 + lane;
        float dc = distf(n);
        bool pr = (dc < md) || (dc == md && n < mi);
        unsigned mask = __ballot_sync(0xffffffffu, pr);
        while (mask) {
            int l = __ffs(mask) - 1; mask &= mask - 1;
            float cd = __shfl_sync(0xffffffffu, dc, l);
            int   ci = it*32 + l;
            if (cd < md || (cd == md && ci < mi)) {
                if (lane == ml) { hd = cd; hi = ci; }
                worst32();
            }
        }
    }
    d_knn[warp*KS + lane] = hi;
}

// ---------------- K3: gather + layer0 tf32-MMA GEMM + stats ----------------
// Block: 64 out x 256 pos, 512 thr = 16 warps (4 out-stripes x 4 pos-windows).
// W smem [64][76] (A-frag banks 12g+tg, CF). H smem [72][264] (264 mod 32 = 8,
// B-frag banks 8tg+g, all 32 distinct -> CF); k rows 67..71 zero.
__global__ __launch_bounds__(512, 2) void klayer0(const float* __restrict__ xyz,
                        const float* __restrict__ pts,
                        const float* __restrict__ W,
                        const float* __restrict__ bias) {
    extern __shared__ unsigned smu_[];
    unsigned* sH = smu_;                 // [72][264]
    unsigned* sW = sH + 72*264;          // [64][76]
    float*    sb = (float*)(sW + 64*76); // [64]
    double*   ssum = (double*)(sb + 64);
    double*   ssq  = ssum + 64;

    int t = threadIdx.x;
    for (int i = t; i < 64*72; i += 512) {
        int o = i / 72, k = i - o*72;
        sW[o*76 + k] = (k < C0) ? tf32(W[o*C0 + k]) : 0u;
    }
    if (t < 64) { sb[t] = bias[t]; ssum[t] = 0.0; ssq[t] = 0.0; }
    for (int i = t; i < 5*264; i += 512)
        sH[(67 + i/264)*264 + (i % 264)] = 0u;

    int pos0 = blockIdx.x * 256;
    {   // gather: 2 threads per position
        int p = t >> 1, half = t & 1;
        int pos = pos0 + p;
        int n  = d_knn[pos];
        int b  = pos >> 15;
        const float* pbase = pts + ((size_t)b*NPT + n) * DF;
        if (half == 0) {
            int qi = d_fps[pos >> 5];
            const float* xb = xyz + (size_t)b * NPT * 3;
            sH[0*264 + p] = tf32(xb[3*n]   - xb[3*qi]);
            sH[1*264 + p] = tf32(xb[3*n+1] - xb[3*qi+1]);
            sH[2*264 + p] = tf32(xb[3*n+2] - xb[3*qi+2]);
        }
        const float4* pb = (const float4*)pbase;
#pragma unroll
        for (int c4 = half*8; c4 < half*8 + 8; c4++) {
            float4 v = pb[c4];
            sH[(3+4*c4+0)*264 + p] = tf32(v.x);
            sH[(3+4*c4+1)*264 + p] = tf32(v.y);
            sH[(3+4*c4+2)*264 + p] = tf32(v.z);
            sH[(3+4*c4+3)*264 + p] = tf32(v.w);
        }
    }
    __syncthreads();

    int lane = t & 31, w = t >> 5;
    int g = lane >> 2, tg = lane & 3;
    int out0 = (w & 3) * 16;
    int pw   = (w >> 2) * 64;

    float acc[8][4];
#pragma unroll
    for (int n = 0; n < 8; n++)
#pragma unroll
        for (int j = 0; j < 4; j++) acc[n][j] = 0.0f;

#pragma unroll
    for (int ks = 0; ks < 9; ks++) {
        int k0 = ks * 8;
        unsigned a0 = sW[(out0+g)*76   + k0 + tg];
        unsigned a1 = sW[(out0+g+8)*76 + k0 + tg];
        unsigned a2 = sW[(out0+g)*76   + k0 + tg + 4];
        unsigned a3 = sW[(out0+g+8)*76 + k0 + tg + 4];
#pragma unroll
        for (int n = 0; n < 8; n++) {
            unsigned b0 = sH[(k0+tg)*264   + pw + n*8 + g];
            unsigned b1 = sH[(k0+tg+4)*264 + pw + n*8 + g];
            mma1688(acc[n][0], acc[n][1], acc[n][2], acc[n][3], a0, a1, a2, a3, b0, b1);
        }
    }

    int r0 = out0 + g, r1 = r0 + 8;
    float bf0 = sb[r0], bf1 = sb[r1];
    float s10 = 0.f, s20 = 0.f, s11 = 0.f, s21 = 0.f;
#pragma unroll
    for (int n = 0; n < 8; n++) {
        float c0 = acc[n][0] + bf0, c1 = acc[n][1] + bf0;
        float c2 = acc[n][2] + bf1, c3 = acc[n][3] + bf1;
        int gp = pos0 + pw + n*8 + 2*tg;
        *(float2*)(d_y0 + (size_t)r0*PP + gp) = make_float2(c0, c1);
        *(float2*)(d_y0 + (size_t)r1*PP + gp) = make_float2(c2, c3);
        s10 += c0 + c1; s20 += c0*c0 + c1*c1;
        s11 += c2 + c3; s21 += c2*c2 + c3*c3;
    }
#pragma unroll
    for (int off = 1; off <= 2; off <<= 1) {
        s10 += __shfl_xor_sync(0xffffffffu, s10, off);
        s20 += __shfl_xor_sync(0xffffffffu, s20, off);
        s11 += __shfl_xor_sync(0xffffffffu, s11, off);
        s21 += __shfl_xor_sync(0xffffffffu, s21, off);
    }
    if (tg == 0) {
        atomicAdd(&ssum[r0], (double)s10); atomicAdd(&ssq[r0], (double)s20);
        atomicAdd(&ssum[r1], (double)s11); atomicAdd(&ssq[r1], (double)s21);
    }
    __syncthreads();
    if (t < 64) { atomicAdd(&d_sum[t], ssum[t]); atomicAdd(&d_sq[t], ssq[t]); }
}

// ---------------- finalize BN stats ----------------------------------------
__global__ void kstats(int L, int C) {
    int c = threadIdx.x;
    if (c < C) {
        double cnt = (double)PP;
        double mu  = d_sum[L*128 + c] / cnt;
        double var = d_sq[L*128 + c] / cnt - mu*mu;
        d_mu[L*128 + c] = (float)mu;
        d_rs[L*128 + c] = (float)(1.0 / sqrt(var + 1e-5));
    }
}

// ---------------- K5: layer1 tf32-MMA GEMM (64->64), bn0+relu on load ------
// Block 64 out x 256 pos, 512 thr. W smem [64][68], H [64][264].
__global__ __launch_bounds__(512, 2) void kmid64(const float* __restrict__ W,
                       const float* __restrict__ bias,
                       const float* __restrict__ gam,
                       const float* __restrict__ bet) {
    extern __shared__ unsigned smu_[];
    unsigned* sH = smu_;                  // [64][264]
    unsigned* sW = sH + 64*264;           // [64][68]
    float*    smu = (float*)(sW + 64*68); // [64] x4
    float*    srs = smu + 64;
    float*    sga = srs + 64;
    float*    sbe = sga + 64;
    float*    sb  = sbe + 64;
    double*   ssum = (double*)(sb + 64);
    double*   ssq  = ssum + 64;

    int t = threadIdx.x;
    for (int i = t; i < 64*16; i += 512) {         // float4 W staging
        int o = i >> 4, k4 = i & 15;
        float4 v = *(const float4*)(W + o*64 + k4*4);
        uint4 u; u.x = tf32(v.x); u.y = tf32(v.y); u.z = tf32(v.z); u.w = tf32(v.w);
        *(uint4*)(sW + o*68 + k4*4) = u;
    }
    if (t < 64) {
        sW[t*68 + 64] = 0u; sW[t*68 + 65] = 0u; sW[t*68 + 66] = 0u; sW[t*68 + 67] = 0u;
        smu[t] = d_mu[t]; srs[t] = d_rs[t];
        sga[t] = gam[t];  sbe[t] = bet[t];
        sb[t] = bias[t]; ssum[t] = 0.0; ssq[t] = 0.0;
    }
    __syncthreads();

    int pos0 = blockIdx.x * 256;
    for (int i = t; i < 64*64; i += 512) {        // 64 ch x 64 float4 (256 pos)
        int c = i >> 6, p4 = i & 63;
        float4 v = *(const float4*)(d_y0 + (size_t)c*PP + pos0 + p4*4);
        float mu = smu[c], rs = srs[c], ga = sga[c], be = sbe[c];
        float a0 = ga*(v.x-mu); a0 *= rs; a0 += be; a0 = fmaxf(a0, 0.f);
        float a1 = ga*(v.y-mu); a1 *= rs; a1 += be; a1 = fmaxf(a1, 0.f);
        float a2 = ga*(v.z-mu); a2 *= rs; a2 += be; a2 = fmaxf(a2, 0.f);
        float a3 = ga*(v.w-mu); a3 *= rs; a3 += be; a3 = fmaxf(a3, 0.f);
        uint4 u; u.x = tf32(a0); u.y = tf32(a1); u.z = tf32(a2); u.w = tf32(a3);
        *(uint4*)(sH + c*264 + p4*4) = u;
    }
    __syncthreads();

    int lane = t & 31, w = t >> 5;
    int g = lane >> 2, tg = lane & 3;
    int out0 = (w & 3) * 16;
    int pw   = (w >> 2) * 64;

    float acc[8][4];
#pragma unroll
    for (int n = 0; n < 8; n++)
#pragma unroll
        for (int j = 0; j < 4; j++) acc[n][j] = 0.0f;

#pragma unroll
    for (int ks = 0; ks < 8; ks++) {
        int k0 = ks * 8;
        unsigned a0 = sW[(out0+g)*68   + k0 + tg];
        unsigned a1 = sW[(out0+g+8)*68 + k0 + tg];
        unsigned a2 = sW[(out0+g)*68   + k0 + tg + 4];
        unsigned a3 = sW[(out0+g+8)*68 + k0 + tg + 4];
#pragma unroll
        for (int n = 0; n < 8; n++) {
            unsigned b0 = sH[(k0+tg)*264   + pw + n*8 + g];
            unsigned b1 = sH[(k0+tg+4)*264 + pw + n*8 + g];
            mma1688(acc[n][0], acc[n][1], acc[n][2], acc[n][3], a0, a1, a2, a3, b0, b1);
        }
    }

    int r0 = out0 + g, r1 = r0 + 8;
    float bf0 = sb[r0], bf1 = sb[r1];
    float s10 = 0.f, s20 = 0.f, s11 = 0.f, s21 = 0.f;
#pragma unroll
    for (int n = 0; n < 8; n++) {
        float c0 = acc[n][0] + bf0, c1 = acc[n][1] + bf0;
        float c2 = acc[n][2] + bf1, c3 = acc[n][3] + bf1;
        int gp = pos0 + pw + n*8 + 2*tg;
        *(float2*)(d_y1 + (size_t)r0*PP + gp) = make_float2(c0, c1);
        *(float2*)(d_y1 + (size_t)r1*PP + gp) = make_float2(c2, c3);
        s10 += c0 + c1; s20 += c0*c0 + c1*c1;
        s11 += c2 + c3; s21 += c2*c2 + c3*c3;
    }
#pragma unroll
    for (int off = 1; off <= 2; off <<= 1) {
        s10 += __shfl_xor_sync(0xffffffffu, s10, off);
        s20 += __shfl_xor_sync(0xffffffffu, s20, off);
        s11 += __shfl_xor_sync(0xffffffffu, s11, off);
        s21 += __shfl_xor_sync(0xffffffffu, s21, off);
    }
    if (tg == 0) {
        atomicAdd(&ssum[r0], (double)s10); atomicAdd(&ssq[r0], (double)s20);
        atomicAdd(&ssum[r1], (double)s11); atomicAdd(&ssq[r1], (double)s21);
    }
    __syncthreads();
    if (t < 64) { atomicAdd(&d_sum[128 + t], ssum[t]); atomicAdd(&d_sq[128 + t], ssq[t]); }
}

// ---------------- K7: layer2 tf32-MMA GEMM (64->128) + stats + raw max -----
// Block 128 out x 128 pos, 512 thr = 16 warps (8 out-stripes x 2 pos-windows).
// H stride 136 (mod 32 = 8): B-frag banks 8tg+g, CF.
__global__ __launch_bounds__(512, 3) void klast(const float* __restrict__ W,
                      const float* __restrict__ bias,
                      const float* __restrict__ gam,
                      const float* __restrict__ bet) {
    extern __shared__ unsigned smu_[];
    unsigned* sH = smu_;                   // [64][136]
    unsigned* sW = sH + 64*136;            // [128][68]
    float*    smu = (float*)(sW + 128*68); // [64] x4
    float*    srs = smu + 64;
    float*    sga = srs + 64;
    float*    sbe = sga + 64;
    float*    sb  = sbe + 64;              // [128]
    unsigned* smax = (unsigned*)(sb + 128);// [4][128]
    double*   ssum = (double*)(smax + 4*128);
    double*   ssq  = ssum + 128;

    int t = threadIdx.x;
    for (int i = t; i < 128*16; i += 512) {        // float4 W staging
        int o = i >> 4, k4 = i & 15;
        float4 v = *(const float4*)(W + o*64 + k4*4);
        uint4 u; u.x = tf32(v.x); u.y = tf32(v.y); u.z = tf32(v.z); u.w = tf32(v.w);
        *(uint4*)(sW + o*68 + k4*4) = u;
    }
    if (t < 128) {
        sW[t*68 + 64] = 0u; sW[t*68 + 65] = 0u; sW[t*68 + 66] = 0u; sW[t*68 + 67] = 0u;
        sb[t] = bias[t]; ssum[t] = 0.0; ssq[t] = 0.0;
    }
    if (t < 64) {
        smu[t] = d_mu[128 + t]; srs[t] = d_rs[128 + t];
        sga[t] = gam[t];        sbe[t] = bet[t];
    }
    smax[t] = 0u;                                   // 512 = 4*128
    __syncthreads();

    int pos0 = blockIdx.x * 128;
    for (int i = t; i < 64*32; i += 512) {         // 64 ch x 32 float4 (128 pos)
        int c = i >> 5, p4 = i & 31;
        float4 v = *(const float4*)(d_y1 + (size_t)c*PP + pos0 + p4*4);
        float mu = smu[c], rs = srs[c], ga = sga[c], be = sbe[c];
        float a0 = ga*(v.x-mu); a0 *= rs; a0 += be; a0 = fmaxf(a0, 0.f);
        float a1 = ga*(v.y-mu); a1 *= rs; a1 += be; a1 = fmaxf(a1, 0.f);
        float a2 = ga*(v.z-mu); a2 *= rs; a2 += be; a2 = fmaxf(a2, 0.f);
        float a3 = ga*(v.w-mu); a3 *= rs; a3 += be; a3 = fmaxf(a3, 0.f);
        uint4 u; u.x = tf32(a0); u.y = tf32(a1); u.z = tf32(a2); u.w = tf32(a3);
        *(uint4*)(sH + c*136 + p4*4) = u;
    }
    __syncthreads();

    int lane = t & 31, w = t >> 5;
    int g = lane >> 2, tg = lane & 3;
    int out0 = (w & 7) * 16;
    int pw   = (w >> 3) * 64;

    float acc[8][4];
#pragma unroll
    for (int n = 0; n < 8; n++)
#pragma unroll
        for (int j = 0; j < 4; j++) acc[n][j] = 0.0f;

#pragma unroll
    for (int ks = 0; ks < 8; ks++) {
        int k0 = ks * 8;
        unsigned a0 = sW[(out0+g)*68   + k0 + tg];
        unsigned a1 = sW[(out0+g+8)*68 + k0 + tg];
        unsigned a2 = sW[(out0+g)*68   + k0 + tg + 4];
        unsigned a3 = sW[(out0+g+8)*68 + k0 + tg + 4];
#pragma unroll
        for (int n = 0; n < 8; n++) {
            unsigned b0 = sH[(k0+tg)*136   + pw + n*8 + g];
            unsigned b1 = sH[(k0+tg+4)*136 + pw + n*8 + g];
            mma1688(acc[n][0], acc[n][1], acc[n][2], acc[n][3], a0, a1, a2, a3, b0, b1);
        }
    }

    int r0 = out0 + g, r1 = r0 + 8;
    float bf0 = sb[r0], bf1 = sb[r1];
    float s10 = 0.f, s20 = 0.f, s11 = 0.f, s21 = 0.f;
    float mx00 = -INFINITY, mx01 = -INFINITY;   // r0, windows pw/32, pw/32+1
    float mx10 = -INFINITY, mx11 = -INFINITY;   // r1
#pragma unroll
    for (int n = 0; n < 8; n++) {
        float c0 = acc[n][0] + bf0, c1 = acc[n][1] + bf0;
        float c2 = acc[n][2] + bf1, c3 = acc[n][3] + bf1;
        float p0 = fmaxf(c0, c1), p1 = fmaxf(c2, c3);
        if (n < 4) { mx00 = fmaxf(mx00, p0); mx10 = fmaxf(mx10, p1); }
        else       { mx01 = fmaxf(mx01, p0); mx11 = fmaxf(mx11, p1); }
        s10 += c0 + c1; s20 += c0*c0 + c1*c1;
        s11 += c2 + c3; s21 += c2*c2 + c3*c3;
    }
#pragma unroll
    for (int off = 1; off <= 2; off <<= 1) {
        s10 += __shfl_xor_sync(0xffffffffu, s10, off);
        s20 += __shfl_xor_sync(0xffffffffu, s20, off);
        s11 += __shfl_xor_sync(0xffffffffu, s11, off);
        s21 += __shfl_xor_sync(0xffffffffu, s21, off);
        mx00 = fmaxf(mx00, __shfl_xor_sync(0xffffffffu, mx00, off));
        mx01 = fmaxf(mx01, __shfl_xor_sync(0xffffffffu, mx01, off));
        mx10 = fmaxf(mx10, __shfl_xor_sync(0xffffffffu, mx10, off));
        mx11 = fmaxf(mx11, __shfl_xor_sync(0xffffffffu, mx11, off));
    }
    if (tg == 0) {
        int wb = (pw >> 5);   // 0 or 2
        atomicAdd(&ssum[r0], (double)s10); atomicAdd(&ssq[r0], (double)s20);
        atomicAdd(&ssum[r1], (double)s11); atomicAdd(&ssq[r1], (double)s21);
        atomicMax(&smax[(wb  )*128 + r0], mkey(mx00));
        atomicMax(&smax[(wb+1)*128 + r0], mkey(mx01));
        atomicMax(&smax[(wb  )*128 + r1], mkey(mx10));
        atomicMax(&smax[(wb+1)*128 + r1], mkey(mx11));
    }
    __syncthreads();
    {
        int r = (pos0 >> 5) + (t >> 7);            // 4 windows
        d_rawmax[(size_t)r*C3 + (t & 127)] = smax[t];
    }
    if (t < 128) { atomicAdd(&d_sum[256 + t], ssum[t]); atomicAdd(&d_sq[256 + t], ssq[t]); }
}

// ---------------- K9: decode raw max, bn2+relu, attention partials ---------
__global__ void kpool(const float* __restrict__ gam, const float* __restrict__ bet) {
    int t = threadIdx.x;
    int c = t & 127, half = t >> 7;
    int blk = blockIdx.x;                  // 256 blocks, 16 per batch
    int b = blk >> 4;
    int r0 = blk * 64 + half * 32;
    float mu = d_mu[256 + c], rs = d_rs[256 + c];
    float ga = gam[c], be = bet[c];
    float sum = 0.0f, mx = 0.0f;
    for (int rr = 0; rr < 32; rr++) {
        int r = r0 + rr;
        float f = unkey(d_rawmax[(size_t)r*C3 + c]);
        float v = ga*(f - mu); v *= rs; v += be; v = fmaxf(v, 0.0f);
        d_np[(size_t)r*C3 + c] = v;
        sum += v; mx = fmaxf(mx, v);
    }
    __shared__ float ssm[256], smm[256];
    ssm[t] = sum; smm[t] = mx;
    __syncthreads();
    if (t < 128) {
        sum = ssm[t] + ssm[t + 128];
        mx = fmaxf(smm[t], smm[t + 128]);
        atomicAdd(&d_avgsum[b*C3 + c], (double)sum);
        atomicMax(&d_maxb[b*C3 + c], __float_as_uint(mx)); // v >= 0
    }
}

// ---------------- K10: channel attention (1 block / batch) -----------------
__global__ void katt(const float* __restrict__ aW1, const float* __restrict__ aW2) {
    int b = blockIdx.x;
    int t = threadIdx.x; // 128
    __shared__ float sav[C3], smx[C3], sha[RR], shm[RR];
    sav[t] = (float)(d_avgsum[b*C3 + t] / (double)SS);
    smx[t] = __uint_as_float(d_maxb[b*C3 + t]);
    __syncthreads();
    if (t < RR) {
        float a = 0.0f, m = 0.0f;
        for (int c = 0; c < C3; c++) {
            a = fmaf(aW1[t*C3 + c], sav[c], a);
            m = fmaf(aW1[t*C3 + c], smx[c], m);
        }
        sha[t] = fmaxf(a, 0.0f);
        shm[t] = fmaxf(m, 0.0f);
    }
    __syncthreads();
    float s1 = 0.0f, s2 = 0.0f;
#pragma unroll
    for (int r = 0; r < RR; r++) {
        s1 = fmaf(aW2[t*RR + r], sha[r], s1);
        s2 = fmaf(aW2[t*RR + r], shm[r], s2);
    }
    float x = s1 + s2;
    d_scale[b*C3 + t] = 1.0f / (1.0f + expf(-x));
}

// ---------------- K11: scale + write new_points ----------------------------
__global__ void kout(float* __restrict__ out) {
    size_t i = (size_t)blockIdx.x * 256 + threadIdx.x;
    if (i < (size_t)BB*SS*C3) {
        int c = (int)(i % C3);
        int r = (int)(i / C3);
        int b = r / SS;
        out[OUT_NP_OFF + i] = d_np[i] * d_scale[b*C3 + c];
    }
}

// ---------------------------------------------------------------------------
extern "C" void kernel_launch(void* const* d_in, const int* in_sizes, int n_in,
                              void* d_out, int out_size) {
    const float* xyz  = (const float*)d_in[0];
    const float* pts  = (const float*)d_in[1];
    const float* W0   = (const float*)d_in[2];
    const float* b0   = (const float*)d_in[3];
    const float* g0   = (const float*)d_in[4];
    const float* be0  = (const float*)d_in[5];
    const float* W1   = (const float*)d_in[6];
    const float* b1   = (const float*)d_in[7];
    const float* g1   = (const float*)d_in[8];
    const float* be1  = (const float*)d_in[9];
    const float* W2   = (const float*)d_in[10];
    const float* b2   = (const float*)d_in[11];
    const float* g2   = (const float*)d_in[12];
    const float* be2  = (const float*)d_in[13];
    const float* aW1  = (const float*)d_in[14];
    const float* aW2  = (const float*)d_in[15];
    float* out = (float*)d_out;

    const int SM_FPS = 3*NPT*4;                                        // 49152
    const int SM_L0  = (72*264 + 64*76)*4 + 64*4 + 64*16;              // 96768
    const int SM_L1  = (64*264 + 64*68)*4 + 5*64*4 + 64*16;            // 87296
    const int SM_L2  = (64*136 + 128*68)*4 + 4*64*4 + 128*4 + 4*128*4 + 128*16; // 76288

    cudaFuncSetAttribute(kfps,    cudaFuncAttributeMaxDynamicSharedMemorySize, SM_FPS);
    cudaFuncSetAttribute(klayer0, cudaFuncAttributeMaxDynamicSharedMemorySize, SM_L0);
    cudaFuncSetAttribute(kmid64,  cudaFuncAttributeMaxDynamicSharedMemorySize, SM_L1);
    cudaFuncSetAttribute(klast,   cudaFuncAttributeMaxDynamicSharedMemorySize, SM_L2);

    kzero<<<8, 256>>>();
    kfps<<<BB, 512, SM_FPS>>>(xyz, out);
    kknn<<<(BB*SS*32)/256, 256>>>(xyz);
    klayer0<<<PP/256, 512, SM_L0>>>(xyz, pts, W0, b0);
    kstats<<<1, 128>>>(0, C1);
    kmid64<<<PP/256, 512, SM_L1>>>(W1, b1, g0, be0);
    kstats<<<1, 128>>>(1, C2);
    klast<<<PP/128, 512, SM_L2>>>(W2, b2, g1, be1);
    kstats<<<1, 128>>>(2, C3);
    kpool<<<256, 256>>>(g2, be2);
    katt<<<BB, 128>>>(aW1, aW2);
    kout<<<(BB*SS*C3 + 255)/256, 256>>>(out);
}

// round 17
// speedup vs baseline: 1.3885x; 1.0088x over previous
#include <cuda_runtime.h>
#include <math.h>

#define BB 16
#define NPT 4096
#define SS 1024
#define KS 32
#define DF 64
#define C0 67
#define C1 64
#define C2 64
#define C3 128
#define RR 16
#define PP (BB*SS*KS)            // 524288 positions

#define OUT_XYZ_OFF 0
#define OUT_NP_OFF  ((size_t)BB*SS*3)
#define OUT_FPS_OFF ((size_t)BB*SS*3 + (size_t)BB*SS*C3)

// ---------------- scratch (static device arrays; no allocs) ----------------
__device__ int      d_fps[BB*SS];
__device__ int      d_knn[BB*SS*KS];
__device__ float    d_y0[(size_t)PP*C1];        // POSITION-major [pos][c]
__device__ float    d_y1[(size_t)PP*C2];        // POSITION-major [pos][c]
__device__ unsigned d_rawmax[(size_t)BB*SS*C3]; // per-(row,ch) max of raw y2, keyed
__device__ float    d_np[(size_t)BB*SS*C3];     // pooled, row-major [r][c]
__device__ double   d_sum[3*128];
__device__ double   d_sq[3*128];
__device__ float    d_mu[3*128];
__device__ float    d_rs[3*128];
__device__ double   d_avgsum[BB*C3];
__device__ unsigned d_maxb[BB*C3];
__device__ float    d_scale[BB*C3];

// ---------------- tf32 helpers ---------------------------------------------
__device__ __forceinline__ unsigned tf32(float x) {
    unsigned r;
    asm("cvt.rna.tf32.f32 %0, %1;" : "=r"(r) : "f"(x));
    return r;
}
__device__ __forceinline__ void mma1688(float& c0, float& c1, float& c2, float& c3,
                                        unsigned a0, unsigned a1, unsigned a2, unsigned a3,
                                        unsigned b0, unsigned b1) {
    asm("mma.sync.aligned.m16n8k8.row.col.f32.tf32.tf32.f32 "
        "{%0,%1,%2,%3}, {%4,%5,%6,%7}, {%8,%9}, {%0,%1,%2,%3};"
        : "+f"(c0), "+f"(c1), "+f"(c2), "+f"(c3)
        : "r"(a0), "r"(a1), "r"(a2), "r"(a3), "r"(b0), "r"(b1));
}

// order-preserving float<->uint key (all finite floats)
__device__ __forceinline__ unsigned mkey(float f) {
    unsigned b = __float_as_uint(f);
    return (b & 0x80000000u) ? ~b : (b | 0x80000000u);
}
__device__ __forceinline__ float unkey(unsigned k) {
    unsigned b = (k & 0x80000000u) ? (k & 0x7fffffffu) : ~k;
    return __uint_as_float(b);
}

// ---------------- zero accumulators ----------------------------------------
__global__ void kzero() {
    int t = blockIdx.x * blockDim.x + threadIdx.x;
    if (t < 3*128) { d_sum[t] = 0.0; d_sq[t] = 0.0; }
    if (t < BB*C3) { d_avgsum[t] = 0.0; d_maxb[t] = 0u; }
}

// ---------------- K1: farthest point sampling (1 block / batch) ------------
__global__ __launch_bounds__(512) void kfps(const float* __restrict__ xyz, float* __restrict__ out) {
    int b = blockIdx.x;
    extern __shared__ float sh[];
    float* sx = sh;
    float* sy = sh + NPT;
    float* sz = sh + 2*NPT;
    __shared__ unsigned rb[2][16];
    __shared__ int      ri[2][16];

    int t = threadIdx.x;
    int lane = t & 31, wid = t >> 5;
    const float* xb = xyz + (size_t)b * NPT * 3;
    for (int p = t; p < NPT; p += 512) {
        sx[p] = xb[3*p]; sy[p] = xb[3*p+1]; sz[p] = xb[3*p+2];
    }
    __syncthreads();

    float px[8], py[8], pz[8], dist[8];
#pragma unroll
    for (int j = 0; j < 8; j++) {
        int p = j*512 + t;
        px[j] = sx[p]; py[j] = sy[p]; pz[j] = sz[p];
        dist[j] = INFINITY;
    }

    int far = NPT / 2;
    int ph = 0;
    for (int i = 0; i < SS; i++) {
        if (t == 0) {
            d_fps[b*SS + i] = far;
            out[OUT_XYZ_OFF + (size_t)(b*SS + i)*3 + 0] = sx[far];
            out[OUT_XYZ_OFF + (size_t)(b*SS + i)*3 + 1] = sy[far];
            out[OUT_XYZ_OFF + (size_t)(b*SS + i)*3 + 2] = sz[far];
            out[OUT_FPS_OFF + b*SS + i] = (float)far;
        }
        if (i == SS - 1) break;   // last centroid's successor is never used
        float cx = sx[far], cy = sy[far], cz = sz[far];
        float bv = -1.0f; int bi = 0;
#pragma unroll
        for (int j = 0; j < 8; j++) {
            float dx = __fadd_rn(px[j], -cx);
            float dy = __fadd_rn(py[j], -cy);
            float dz = __fadd_rn(pz[j], -cz);
            float d = __fadd_rn(__fadd_rn(__fmul_rn(dx,dx), __fmul_rn(dy,dy)),
                                __fmul_rn(dz,dz));
            float nd = fminf(dist[j], d);
            dist[j] = nd;
            if (nd > bv) { bv = nd; bi = j*512 + t; }  // lowest idx kept on tie
        }
        unsigned db = __float_as_uint(bv);
        unsigned m  = __reduce_max_sync(0xffffffffu, db);
        unsigned ii = (db == m) ? (unsigned)bi : 0xffffffffu;
        unsigned wi = __reduce_min_sync(0xffffffffu, ii);
        if (lane == 0) { rb[ph][wid] = m; ri[ph][wid] = (int)wi; }
        __syncthreads();
        unsigned m2 = (lane < 16) ? rb[ph][lane] : 0u;
        unsigned mm = __reduce_max_sync(0xffffffffu, m2);
        unsigned i2 = (lane < 16 && m2 == mm) ? (unsigned)ri[ph][lane] : 0xffffffffu;
        far = (int)__reduce_min_sync(0xffffffffu, i2);
        ph ^= 1;
    }
}

// ---------------- K2: 32-NN per sampled point (warp per query) -------------
__global__ void kknn(const float* __restrict__ xyz) {
    int warp = (blockIdx.x * blockDim.x + threadIdx.x) >> 5;
    int lane = threadIdx.x & 31;
    if (warp >= BB*SS) return;
    int b = warp / SS;
    int qi = d_fps[warp];
    const float* xb = xyz + (size_t)b * NPT * 3;
    float qx = xb[3*qi], qy = xb[3*qi+1], qz = xb[3*qi+2];
    float ss2 = qx*qx + qy*qy + qz*qz;

    auto distf = [&](int n) {
        float x = xb[3*n], y = xb[3*n+1], z = xb[3*n+2];
        float dot = x*qx + y*qy + z*qz;
        float nn2 = x*x + y*y + z*z;
        return -2.0f*dot + ss2 + nn2;
    };

    float hd = distf(lane);
    int   hi = lane;
    float md; int mi, ml;
    auto worst32 = [&]() {
        unsigned key = __float_as_uint(hd);       // dists >= 0
        unsigned m = __reduce_max_sync(0xffffffffu, key);
        unsigned im = __reduce_max_sync(0xffffffffu,
                          (key == m) ? (unsigned)hi : 0u);
        unsigned lm = __ballot_sync(0xffffffffu,
                          (key == m) && ((unsigned)hi == im));
        md = __uint_as_float(m);
        mi = (int)im;
        ml = 31 - __clz(lm);
    };
    worst32();

    for (int it = 1; it < NPT/32; it++) {
        int n = it*32 + lane;
        float dc = distf(n);
        bool pr = (dc < md) || (dc == md && n < mi);
        unsigned mask = __ballot_sync(0xffffffffu, pr);
        while (mask) {
            int l = __ffs(mask) - 1; mask &= mask - 1;
            float cd = __shfl_sync(0xffffffffu, dc, l);
            int   ci = it*32 + l;
            if (cd < md || (cd == md && ci < mi)) {
                if (lane == ml) { hd = cd; hi = ci; }
                worst32();
            }
        }
    }
    d_knn[warp*KS + lane] = hi;
}

// ---------------- K3: gather + layer0 tf32-MMA GEMM + stats ----------------
// Block: 64 out x 256 pos, 512 thr = 16 warps (4 out-stripes x 4 pos-windows).
// W smem [64][76] (A-frag banks 12g+tg, CF).
// H smem POS-major [256][68] (68 mod 32 = 4 -> B-frag banks 4g+tg, CF);
// staging writes are 17 uint4 per position (vectorized).
__global__ __launch_bounds__(512, 2) void klayer0(const float* __restrict__ xyz,
                        const float* __restrict__ pts,
                        const float* __restrict__ W,
                        const float* __restrict__ bias) {
    extern __shared__ unsigned smu_[];
    unsigned* sH = smu_;                 // [256][68]
    unsigned* sW = sH + 256*68;          // [64][76]
    float*    sb = (float*)(sW + 64*76); // [64]
    double*   ssum = (double*)(sb + 64);
    double*   ssq  = ssum + 64;

    int t = threadIdx.x;
    for (int i = t; i < 64*72; i += 512) {
        int o = i / 72, k = i - o*72;
        sW[o*76 + k] = (k < C0) ? tf32(W[o*C0 + k]) : 0u;
    }
    if (t < 64) { sb[t] = bias[t]; ssum[t] = 0.0; ssq[t] = 0.0; }

    int pos0 = blockIdx.x * 256;
    if (t < 256) {   // gather: 1 thread per position, vectorized smem writes
        int p = t;
        int pos = pos0 + p;
        int n  = d_knn[pos];
        int b  = pos >> 15;
        int qi = d_fps[pos >> 5];
        const float* xb = xyz + (size_t)b * NPT * 3;
        const float4* pb = (const float4*)(pts + ((size_t)b*NPT + n) * DF);
        float v[68];
        v[0] = xb[3*n]   - xb[3*qi];
        v[1] = xb[3*n+1] - xb[3*qi+1];
        v[2] = xb[3*n+2] - xb[3*qi+2];
#pragma unroll
        for (int c4 = 0; c4 < 16; c4++) {
            float4 f = pb[c4];
            v[3+4*c4] = f.x; v[4+4*c4] = f.y; v[5+4*c4] = f.z; v[6+4*c4] = f.w;
        }
        v[67] = 0.0f;
        unsigned* hr = sH + p*68;
#pragma unroll
        for (int j = 0; j < 17; j++) {
            uint4 u;
            u.x = tf32(v[4*j]);   u.y = tf32(v[4*j+1]);
            u.z = tf32(v[4*j+2]); u.w = tf32(v[4*j+3]);
            *(uint4*)(hr + 4*j) = u;
        }
    }
    __syncthreads();

    int lane = t & 31, w = t >> 5;
    int g = lane >> 2, tg = lane & 3;
    int out0 = (w & 3) * 16;
    int pw   = (w >> 2) * 64;

    float acc[8][4];
#pragma unroll
    for (int n = 0; n < 8; n++)
#pragma unroll
        for (int j = 0; j < 4; j++) acc[n][j] = 0.0f;

#pragma unroll
    for (int ks = 0; ks < 9; ks++) {
        int k0 = ks * 8;
        unsigned a0 = sW[(out0+g)*76   + k0 + tg];
        unsigned a1 = sW[(out0+g+8)*76 + k0 + tg];
        unsigned a2 = sW[(out0+g)*76   + k0 + tg + 4];
        unsigned a3 = sW[(out0+g+8)*76 + k0 + tg + 4];
#pragma unroll
        for (int n = 0; n < 8; n++) {
            unsigned b0 = sH[(pw + n*8 + g)*68 + k0 + tg];
            unsigned b1 = sH[(pw + n*8 + g)*68 + k0 + tg + 4];
            mma1688(acc[n][0], acc[n][1], acc[n][2], acc[n][3], a0, a1, a2, a3, b0, b1);
        }
    }

    int r0 = out0 + g, r1 = r0 + 8;
    float bf0 = sb[r0], bf1 = sb[r1];
    float s10 = 0.f, s20 = 0.f, s11 = 0.f, s21 = 0.f;
#pragma unroll
    for (int n = 0; n < 8; n++) {
        float c0 = acc[n][0] + bf0, c1 = acc[n][1] + bf0;
        float c2 = acc[n][2] + bf1, c3 = acc[n][3] + bf1;
        int gp = pos0 + pw + n*8 + 2*tg;
        d_y0[(size_t)gp*C1 + r0]     = c0;
        d_y0[(size_t)(gp+1)*C1 + r0] = c1;
        d_y0[(size_t)gp*C1 + r1]     = c2;
        d_y0[(size_t)(gp+1)*C1 + r1] = c3;
        s10 += c0 + c1; s20 += c0*c0 + c1*c1;
        s11 += c2 + c3; s21 += c2*c2 + c3*c3;
    }
#pragma unroll
    for (int off = 1; off <= 2; off <<= 1) {
        s10 += __shfl_xor_sync(0xffffffffu, s10, off);
        s20 += __shfl_xor_sync(0xffffffffu, s20, off);
        s11 += __shfl_xor_sync(0xffffffffu, s11, off);
        s21 += __shfl_xor_sync(0xffffffffu, s21, off);
    }
    if (tg == 0) {
        atomicAdd(&ssum[r0], (double)s10); atomicAdd(&ssq[r0], (double)s20);
        atomicAdd(&ssum[r1], (double)s11); atomicAdd(&ssq[r1], (double)s21);
    }
    __syncthreads();
    if (t < 64) { atomicAdd(&d_sum[t], ssum[t]); atomicAdd(&d_sq[t], ssq[t]); }
}

// ---------------- finalize BN stats ----------------------------------------
__global__ void kstats(int L, int C) {
    int c = threadIdx.x;
    if (c < C) {
        double cnt = (double)PP;
        double mu  = d_sum[L*128 + c] / cnt;
        double var = d_sq[L*128 + c] / cnt - mu*mu;
        d_mu[L*128 + c] = (float)mu;
        d_rs[L*128 + c] = (float)(1.0 / sqrt(var + 1e-5));
    }
}

// ---------------- K5: layer1 tf32-MMA GEMM (64->64), bn0+relu on load ------
// Block 64 out x 256 pos, 512 thr. W [64][68], H POS-major [256][68].
// Staging: fully vectorized (float4 in, uint4 out, zero transpose).
__global__ __launch_bounds__(512, 2) void kmid64(const float* __restrict__ W,
                       const float* __restrict__ bias,
                       const float* __restrict__ gam,
                       const float* __restrict__ bet) {
    extern __shared__ unsigned smu_[];
    unsigned* sH = smu_;                  // [256][68]
    unsigned* sW = sH + 256*68;           // [64][68]
    float*    smu = (float*)(sW + 64*68); // [64] x4
    float*    srs = smu + 64;
    float*    sga = srs + 64;
    float*    sbe = sga + 64;
    float*    sb  = sbe + 64;
    double*   ssum = (double*)(sb + 64);
    double*   ssq  = ssum + 64;

    int t = threadIdx.x;
    for (int i = t; i < 64*16; i += 512) {         // float4 W staging
        int o = i >> 4, k4 = i & 15;
        float4 v = *(const float4*)(W + o*64 + k4*4);
        uint4 u; u.x = tf32(v.x); u.y = tf32(v.y); u.z = tf32(v.z); u.w = tf32(v.w);
        *(uint4*)(sW + o*68 + k4*4) = u;
    }
    if (t < 64) {
        sW[t*68 + 64] = 0u; sW[t*68 + 65] = 0u; sW[t*68 + 66] = 0u; sW[t*68 + 67] = 0u;
        smu[t] = d_mu[t]; srs[t] = d_rs[t];
        sga[t] = gam[t];  sbe[t] = bet[t];
        sb[t] = bias[t]; ssum[t] = 0.0; ssq[t] = 0.0;
    }
    if (t < 256) {
        sH[t*68 + 64] = 0u; sH[t*68 + 65] = 0u; sH[t*68 + 66] = 0u; sH[t*68 + 67] = 0u;
    }
    __syncthreads();

    int pos0 = blockIdx.x * 256;
    for (int i = t; i < 256*16; i += 512) {        // 256 pos x 16 float4
        int p = i >> 4, c4 = i & 15;
        float4 v = *(const float4*)(d_y0 + (size_t)(pos0 + p)*C1 + c4*4);
        int c = c4*4;
        float a0 = sga[c+0]*(v.x-smu[c+0]); a0 *= srs[c+0]; a0 += sbe[c+0]; a0 = fmaxf(a0, 0.f);
        float a1 = sga[c+1]*(v.y-smu[c+1]); a1 *= srs[c+1]; a1 += sbe[c+1]; a1 = fmaxf(a1, 0.f);
        float a2 = sga[c+2]*(v.z-smu[c+2]); a2 *= srs[c+2]; a2 += sbe[c+2]; a2 = fmaxf(a2, 0.f);
        float a3 = sga[c+3]*(v.w-smu[c+3]); a3 *= srs[c+3]; a3 += sbe[c+3]; a3 = fmaxf(a3, 0.f);
        uint4 u; u.x = tf32(a0); u.y = tf32(a1); u.z = tf32(a2); u.w = tf32(a3);
        *(uint4*)(sH + p*68 + c4*4) = u;
    }
    __syncthreads();

    int lane = t & 31, w = t >> 5;
    int g = lane >> 2, tg = lane & 3;
    int out0 = (w & 3) * 16;
    int pw   = (w >> 2) * 64;

    float acc[8][4];
#pragma unroll
    for (int n = 0; n < 8; n++)
#pragma unroll
        for (int j = 0; j < 4; j++) acc[n][j] = 0.0f;

#pragma unroll
    for (int ks = 0; ks < 8; ks++) {
        int k0 = ks * 8;
        unsigned a0 = sW[(out0+g)*68   + k0 + tg];
        unsigned a1 = sW[(out0+g+8)*68 + k0 + tg];
        unsigned a2 = sW[(out0+g)*68   + k0 + tg + 4];
        unsigned a3 = sW[(out0+g+8)*68 + k0 + tg + 4];
#pragma unroll
        for (int n = 0; n < 8; n++) {
            unsigned b0 = sH[(pw + n*8 + g)*68 + k0 + tg];
            unsigned b1 = sH[(pw + n*8 + g)*68 + k0 + tg + 4];
            mma1688(acc[n][0], acc[n][1], acc[n][2], acc[n][3], a0, a1, a2, a3, b0, b1);
        }
    }

    int r0 = out0 + g, r1 = r0 + 8;
    float bf0 = sb[r0], bf1 = sb[r1];
    float s10 = 0.f, s20 = 0.f, s11 = 0.f, s21 = 0.f;
#pragma unroll
    for (int n = 0; n < 8; n++) {
        float c0 = acc[n][0] + bf0, c1 = acc[n][1] + bf0;
        float c2 = acc[n][2] + bf1, c3 = acc[n][3] + bf1;
        int gp = pos0 + pw + n*8 + 2*tg;
        d_y1[(size_t)gp*C2 + r0]     = c0;
        d_y1[(size_t)(gp+1)*C2 + r0] = c1;
        d_y1[(size_t)gp*C2 + r1]     = c2;
        d_y1[(size_t)(gp+1)*C2 + r1] = c3;
        s10 += c0 + c1; s20 += c0*c0 + c1*c1;
        s11 += c2 + c3; s21 += c2*c2 + c3*c3;
    }
#pragma unroll
    for (int off = 1; off <= 2; off <<= 1) {
        s10 += __shfl_xor_sync(0xffffffffu, s10, off);
        s20 += __shfl_xor_sync(0xffffffffu, s20, off);
        s11 += __shfl_xor_sync(0xffffffffu, s11, off);
        s21 += __shfl_xor_sync(0xffffffffu, s21, off);
    }
    if (tg == 0) {
        atomicAdd(&ssum[r0], (double)s10); atomicAdd(&ssq[r0], (double)s20);
        atomicAdd(&ssum[r1], (double)s11); atomicAdd(&ssq[r1], (double)s21);
    }
    __syncthreads();
    if (t < 64) { atomicAdd(&d_sum[128 + t], ssum[t]); atomicAdd(&d_sq[128 + t], ssq[t]); }
}

// ---------------- K7: layer2 tf32-MMA GEMM (64->128) + stats + raw max -----
// Block 128 out x 128 pos, 512 thr = 16 warps (8 out-stripes x 2 pos-windows).
// H POS-major [128][68].
__global__ __launch_bounds__(512, 3) void klast(const float* __restrict__ W,
                      const float* __restrict__ bias,
                      const float* __restrict__ gam,
                      const float* __restrict__ bet) {
    extern __shared__ unsigned smu_[];
    unsigned* sH = smu_;                   // [128][68]
    unsigned* sW = sH + 128*68;            // [128][68]
    float*    smu = (float*)(sW + 128*68); // [64] x4
    float*    srs = smu + 64;
    float*    sga = srs + 64;
    float*    sbe = sga + 64;
    float*    sb  = sbe + 64;              // [128]
    unsigned* smax = (unsigned*)(sb + 128);// [4][128]
    double*   ssum = (double*)(smax + 4*128);
    double*   ssq  = ssum + 128;

    int t = threadIdx.x;
    for (int i = t; i < 128*16; i += 512) {        // float4 W staging
        int o = i >> 4, k4 = i & 15;
        float4 v = *(const float4*)(W + o*64 + k4*4);
        uint4 u; u.x = tf32(v.x); u.y = tf32(v.y); u.z = tf32(v.z); u.w = tf32(v.w);
        *(uint4*)(sW + o*68 + k4*4) = u;
    }
    if (t < 128) {
        sW[t*68 + 64] = 0u; sW[t*68 + 65] = 0u; sW[t*68 + 66] = 0u; sW[t*68 + 67] = 0u;
        sH[t*68 + 64] = 0u; sH[t*68 + 65] = 0u; sH[t*68 + 66] = 0u; sH[t*68 + 67] = 0u;
        sb[t] = bias[t]; ssum[t] = 0.0; ssq[t] = 0.0;
    }
    if (t < 64) {
        smu[t] = d_mu[128 + t]; srs[t] = d_rs[128 + t];
        sga[t] = gam[t];        sbe[t] = bet[t];
    }
    smax[t] = 0u;                                   // 512 = 4*128
    __syncthreads();

    int pos0 = blockIdx.x * 128;
    for (int i = t; i < 128*16; i += 512) {        // 128 pos x 16 float4
        int p = i >> 4, c4 = i & 15;
        float4 v = *(const float4*)(d_y1 + (size_t)(pos0 + p)*C2 + c4*4);
        int c = c4*4;
        float a0 = sga[c+0]*(v.x-smu[c+0]); a0 *= srs[c+0]; a0 += sbe[c+0]; a0 = fmaxf(a0, 0.f);
        float a1 = sga[c+1]*(v.y-smu[c+1]); a1 *= srs[c+1]; a1 += sbe[c+1]; a1 = fmaxf(a1, 0.f);
        float a2 = sga[c+2]*(v.z-smu[c+2]); a2 *= srs[c+2]; a2 += sbe[c+2]; a2 = fmaxf(a2, 0.f);
        float a3 = sga[c+3]*(v.w-smu[c+3]); a3 *= srs[c+3]; a3 += sbe[c+3]; a3 = fmaxf(a3, 0.f);
        uint4 u; u.x = tf32(a0); u.y = tf32(a1); u.z = tf32(a2); u.w = tf32(a3);
        *(uint4*)(sH + p*68 + c4*4) = u;
    }
    __syncthreads();

    int lane = t & 31, w = t >> 5;
    int g = lane >> 2, tg = lane & 3;
    int out0 = (w & 7) * 16;
    int pw   = (w >> 3) * 64;

    float acc[8][4];
#pragma unroll
    for (int n = 0; n < 8; n++)
#pragma unroll
        for (int j = 0; j < 4; j++) acc[n][j] = 0.0f;

#pragma unroll
    for (int ks = 0; ks < 8; ks++) {
        int k0 = ks * 8;
        unsigned a0 = sW[(out0+g)*68   + k0 + tg];
        unsigned a1 = sW[(out0+g+8)*68 + k0 + tg];
        unsigned a2 = sW[(out0+g)*68   + k0 + tg + 4];
        unsigned a3 = sW[(out0+g+8)*68 + k0 + tg + 4];
#pragma unroll
        for (int n = 0; n < 8; n++) {
            unsigned b0 = sH[(pw + n*8 + g)*68 + k0 + tg];
            unsigned b1 = sH[(pw + n*8 + g)*68 + k0 + tg + 4];
            mma1688(acc[n][0], acc[n][1], acc[n][2], acc[n][3], a0, a1, a2, a3, b0, b1);
        }
    }

    int r0 = out0 + g, r1 = r0 + 8;
    float bf0 = sb[r0], bf1 = sb[r1];
    float s10 = 0.f, s20 = 0.f, s11 = 0.f, s21 = 0.f;
    float mx00 = -INFINITY, mx01 = -INFINITY;   // r0, windows pw/32, pw/32+1
    float mx10 = -INFINITY, mx11 = -INFINITY;   // r1
#pragma unroll
    for (int n = 0; n < 8; n++) {
        float c0 = acc[n][0] + bf0, c1 = acc[n][1] + bf0;
        float c2 = acc[n][2] + bf1, c3 = acc[n][3] + bf1;
        float p0 = fmaxf(c0, c1), p1 = fmaxf(c2, c3);
        if (n < 4) { mx00 = fmaxf(mx00, p0); mx10 = fmaxf(mx10, p1); }
        else       { mx01 = fmaxf(mx01, p0); mx11 = fmaxf(mx11, p1); }
        s10 += c0 + c1; s20 += c0*c0 + c1*c1;
        s11 += c2 + c3; s21 += c2*c2 + c3*c3;
    }
#pragma unroll
    for (int off = 1; off <= 2; off <<= 1) {
        s10 += __shfl_xor_sync(0xffffffffu, s10, off);
        s20 += __shfl_xor_sync(0xffffffffu, s20, off);
        s11 += __shfl_xor_sync(0xffffffffu, s11, off);
        s21 += __shfl_xor_sync(0xffffffffu, s21, off);
        mx00 = fmaxf(mx00, __shfl_xor_sync(0xffffffffu, mx00, off));
        mx01 = fmaxf(mx01, __shfl_xor_sync(0xffffffffu, mx01, off));
        mx10 = fmaxf(mx10, __shfl_xor_sync(0xffffffffu, mx10, off));
        mx11 = fmaxf(mx11, __shfl_xor_sync(0xffffffffu, mx11, off));
    }
    if (tg == 0) {
        int wb = (pw >> 5);   // 0 or 2
        atomicAdd(&ssum[r0], (double)s10); atomicAdd(&ssq[r0], (double)s20);
        atomicAdd(&ssum[r1], (double)s11); atomicAdd(&ssq[r1], (double)s21);
        atomicMax(&smax[(wb  )*128 + r0], mkey(mx00));
        atomicMax(&smax[(wb+1)*128 + r0], mkey(mx01));
        atomicMax(&smax[(wb  )*128 + r1], mkey(mx10));
        atomicMax(&smax[(wb+1)*128 + r1], mkey(mx11));
    }
    __syncthreads();
    {
        int r = (pos0 >> 5) + (t >> 7);            // 4 windows
        d_rawmax[(size_t)r*C3 + (t & 127)] = smax[t];
    }
    if (t < 128) { atomicAdd(&d_sum[256 + t], ssum[t]); atomicAdd(&d_sq[256 + t], ssq[t]); }
}

// ---------------- K9: decode raw max, bn2+relu, attention partials ---------
__global__ void kpool(const float* __restrict__ gam, const float* __restrict__ bet) {
    int t = threadIdx.x;
    int c = t & 127, half = t >> 7;
    int blk = blockIdx.x;                  // 256 blocks, 16 per batch
    int b = blk >> 4;
    int r0 = blk * 64 + half * 32;
    float mu = d_mu[256 + c], rs = d_rs[256 + c];
    float ga = gam[c], be = bet[c];
    float sum = 0.0f, mx = 0.0f;
    for (int rr = 0; rr < 32; rr++) {
        int r = r0 + rr;
        float f = unkey(d_rawmax[(size_t)r*C3 + c]);
        float v = ga*(f - mu); v *= rs; v += be; v = fmaxf(v, 0.0f);
        d_np[(size_t)r*C3 + c] = v;
        sum += v; mx = fmaxf(mx, v);
    }
    __shared__ float ssm[256], smm[256];
    ssm[t] = sum; smm[t] = mx;
    __syncthreads();
    if (t < 128) {
        sum = ssm[t] + ssm[t + 128];
        mx = fmaxf(smm[t], smm[t + 128]);
        atomicAdd(&d_avgsum[b*C3 + c], (double)sum);
        atomicMax(&d_maxb[b*C3 + c], __float_as_uint(mx)); // v >= 0
    }
}

// ---------------- K10: channel attention (1 block / batch) -----------------
__global__ void katt(const float* __restrict__ aW1, const float* __restrict__ aW2) {
    int b = blockIdx.x;
    int t = threadIdx.x; // 128
    __shared__ float sav[C3], smx[C3], sha[RR], shm[RR];
    sav[t] = (float)(d_avgsum[b*C3 + t] / (double)SS);
    smx[t] = __uint_as_float(d_maxb[b*C3 + t]);
    __syncthreads();
    if (t < RR) {
        float a = 0.0f, m = 0.0f;
        for (int c = 0; c < C3; c++) {
            a = fmaf(aW1[t*C3 + c], sav[c], a);
            m = fmaf(aW1[t*C3 + c], smx[c], m);
        }
        sha[t] = fmaxf(a, 0.0f);
        shm[t] = fmaxf(m, 0.0f);
    }
    __syncthreads();
    float s1 = 0.0f, s2 = 0.0f;
#pragma unroll
    for (int r = 0; r < RR; r++) {
        s1 = fmaf(aW2[t*RR + r], sha[r], s1);
        s2 = fmaf(aW2[t*RR + r], shm[r], s2);
    }
    float x = s1 + s2;
    d_scale[b*C3 + t] = 1.0f / (1.0f + expf(-x));
}

// ---------------- K11: scale + write new_points ----------------------------
__global__ void kout(float* __restrict__ out) {
    size_t i = (size_t)blockIdx.x * 256 + threadIdx.x;
    if (i < (size_t)BB*SS*C3) {
        int c = (int)(i % C3);
        int r = (int)(i / C3);
        int b = r / SS;
        out[OUT_NP_OFF + i] = d_np[i] * d_scale[b*C3 + c];
    }
}

// ---------------------------------------------------------------------------
extern "C" void kernel_launch(void* const* d_in, const int* in_sizes, int n_in,
                              void* d_out, int out_size) {
    const float* xyz  = (const float*)d_in[0];
    const float* pts  = (const float*)d_in[1];
    const float* W0   = (const float*)d_in[2];
    const float* b0   = (const float*)d_in[3];
    const float* g0   = (const float*)d_in[4];
    const float* be0  = (const float*)d_in[5];
    const float* W1   = (const float*)d_in[6];
    const float* b1   = (const float*)d_in[7];
    const float* g1   = (const float*)d_in[8];
    const float* be1  = (const float*)d_in[9];
    const float* W2   = (const float*)d_in[10];
    const float* b2   = (const float*)d_in[11];
    const float* g2   = (const float*)d_in[12];
    const float* be2  = (const float*)d_in[13];
    const float* aW1  = (const float*)d_in[14];
    const float* aW2  = (const float*)d_in[15];
    float* out = (float*)d_out;

    const int SM_FPS = 3*NPT*4;                                        // 49152
    const int SM_L0  = (256*68 + 64*76)*4 + 64*4 + 64*16;              // 90368
    const int SM_L1  = (256*68 + 64*68)*4 + 5*64*4 + 64*16;            // 89344
    const int SM_L2  = (128*68 + 128*68)*4 + 4*64*4 + 128*4 + 4*128*4 + 128*16; // 75264

    cudaFuncSetAttribute(kfps,    cudaFuncAttributeMaxDynamicSharedMemorySize, SM_FPS);
    cudaFuncSetAttribute(klayer0, cudaFuncAttributeMaxDynamicSharedMemorySize, SM_L0);
    cudaFuncSetAttribute(kmid64,  cudaFuncAttributeMaxDynamicSharedMemorySize, SM_L1);
    cudaFuncSetAttribute(klast,   cudaFuncAttributeMaxDynamicSharedMemorySize, SM_L2);

    kzero<<<8, 256>>>();
    kfps<<<BB, 512, SM_FPS>>>(xyz, out);
    kknn<<<(BB*SS*32)/256, 256>>>(xyz);
    klayer0<<<PP/256, 512, SM_L0>>>(xyz, pts, W0, b0);
    kstats<<<1, 128>>>(0, C1);
    kmid64<<<PP/256, 512, SM_L1>>>(W1, b1, g0, be0);
    kstats<<<1, 128>>>(1, C2);
    klast<<<PP/128, 512, SM_L2>>>(W2, b2, g1, be1);
    kstats<<<1, 128>>>(2, C3);
    kpool<<<256, 256>>>(g2, be2);
    katt<<<BB, 128>>>(aW1, aW2);
    kout<<<(BB*SS*C3 + 255)/256, 256>>>(out);
}